// round 1
// baseline (speedup 1.0000x reference)
#include <cuda_runtime.h>
#include <math.h>

// ---------------- Problem constants (fixed by the dataset) ----------------
#define NROWS 16384      // N
#define NMEAS 5120       // n
#define NB    500        // batch
#define MSEC  32         // section size M
#define SIGMA2f 0.2f
#define SCALEf  3.1622776601683795f   // sqrt(n*P/L) = sqrt(10)
#define MAXITR 4

// ---------------- Scratch (device globals; no allocation allowed) ---------
__device__ float  g_y[NMEAS * NB];
__device__ float  g_t[NMEAS * NB];
__device__ float  g_s[NROWS * NB];
__device__ double g_taa;
__device__ float  g_colacc[NB];
__device__ float  g_coef[512];   // SCALE / tau2 per batch column (500 used)

// ---------------- small helper kernels ------------------------------------
__global__ void init_scalars_kernel() {
    if (threadIdx.x == 0) g_taa = 0.0;
}

__global__ void zero_colacc_kernel() {
    int c = threadIdx.x;
    if (c < NB) g_colacc[c] = 0.0f;
}

// sum of squares of A (83.9M floats) -> g_taa (double)
__global__ void reduce_sq_kernel(const float* __restrict__ a, long n4) {
    double acc = 0.0;
    const float4* p = (const float4*)a;
    for (long i = (long)blockIdx.x * blockDim.x + threadIdx.x; i < n4;
         i += (long)gridDim.x * blockDim.x) {
        float4 v = p[i];
        acc += (double)v.x * v.x + (double)v.y * v.y +
               (double)v.z * v.z + (double)v.w * v.w;
    }
    __shared__ double sm[256];
    sm[threadIdx.x] = acc;
    __syncthreads();
    for (int s = 128; s > 0; s >>= 1) {
        if (threadIdx.x < s) sm[threadIdx.x] += sm[threadIdx.x + s];
        __syncthreads();
    }
    if (threadIdx.x == 0) atomicAdd(&g_taa, sm[0]);
}

// column sums of t*t : 40 blocks x 128 rows each, one thread per column
__global__ void colsum_kernel() {
    int col = threadIdx.x;
    if (col >= NB) return;
    int r0 = blockIdx.x * 128;
    float acc = 0.0f;
    for (int rr = 0; rr < 128; rr++) {
        float v = g_t[(size_t)(r0 + rr) * NB + col];
        acc += v * v;
    }
    atomicAdd(&g_colacc[col], acc);
}

// tau2 / coef finalize
__global__ void finalize_kernel(const float* __restrict__ gamma, int iter) {
    int c = threadIdx.x;
    if (c >= NB) return;
    float taa = (float)g_taa;
    float tww = taa;                 // W = A^T -> identical sum of squares
    float g = gamma[iter];
    float v2 = (g_colacc[c] - (float)MSEC * SIGMA2f) / taa;
    float tau2 = v2 / (float)NROWS * ((float)NROWS + (g * g - 2.0f * g) * (float)MSEC)
               + g * g * tww * SIGMA2f / (float)NROWS;
    g_coef[c] = SCALEf / tau2;
}

// ---------------- GEMM 1: out = pre + sign * (A @ X) over [rowsx500] ------
// first != 0 : pre = noise, sign=+1, write g_y AND g_t, X = x_in
// first == 0 : pre = g_y,   sign=-1, write g_t only,   X = g_s
__global__ __launch_bounds__(256, 2)
void gemm_n_kernel(const float* __restrict__ Am, const float* __restrict__ Xin,
                   const float* __restrict__ noise, int first, int K)
{
    __shared__ float As[8][128];
    __shared__ float Bs[8][128];

    const float* X   = first ? Xin   : g_s;
    const float* pre = first ? noise : g_y;
    const float  sign = first ? 1.0f : -1.0f;

    int tid = threadIdx.x;
    int row0 = blockIdx.x * 128, col0 = blockIdx.y * 128;
    int arow = tid >> 1, ac4 = tid & 1;       // A tile loader: 128 rows x 2 float4
    int bk = tid >> 5, bc = tid & 31;         // B tile loader: 8 rows x 32 float4
    int tm = tid >> 4, tn = tid & 15;

    float acc[8][8];
    #pragma unroll
    for (int i = 0; i < 8; i++)
        #pragma unroll
        for (int j = 0; j < 8; j++) acc[i][j] = 0.0f;

    const float* aptr = Am + (size_t)(row0 + arow) * K + ac4 * 4;
    int bcol = col0 + bc * 4;
    bool bvalid = (bcol < NB);   // 500 % 4 == 0 -> float4 fully valid or fully OOB

    for (int k0 = 0; k0 < K; k0 += 8) {
        float4 av = *(const float4*)(aptr + k0);
        float4 bv = make_float4(0.f, 0.f, 0.f, 0.f);
        if (bvalid) bv = *(const float4*)(X + (size_t)(k0 + bk) * NB + bcol);
        As[ac4 * 4 + 0][arow] = av.x;
        As[ac4 * 4 + 1][arow] = av.y;
        As[ac4 * 4 + 2][arow] = av.z;
        As[ac4 * 4 + 3][arow] = av.w;
        *(float4*)&Bs[bk][bc * 4] = bv;
        __syncthreads();
        #pragma unroll
        for (int kk = 0; kk < 8; kk++) {
            float a[8], b[8];
            *(float4*)(a)     = *(const float4*)&As[kk][tm * 8];
            *(float4*)(a + 4) = *(const float4*)&As[kk][tm * 8 + 4];
            *(float4*)(b)     = *(const float4*)&Bs[kk][tn * 8];
            *(float4*)(b + 4) = *(const float4*)&Bs[kk][tn * 8 + 4];
            #pragma unroll
            for (int i = 0; i < 8; i++)
                #pragma unroll
                for (int j = 0; j < 8; j++) acc[i][j] += a[i] * b[j];
        }
        __syncthreads();
    }

    #pragma unroll
    for (int i = 0; i < 8; i++) {
        int row = row0 + tm * 8 + i;
        #pragma unroll
        for (int j = 0; j < 8; j++) {
            int col = col0 + tn * 8 + j;
            if (col < NB) {
                size_t idx = (size_t)row * NB + col;
                float v = pre[idx] + sign * acc[i][j];
                g_t[idx] = v;
                if (first) g_y[idx] = v;
            }
        }
    }
}

// ---------------- GEMM 2 + shrink: s = softmax_sec((s + g*(W @ t)) * coef) -
// iter==0: s treated as zero (skip read). iter==3: write to out_final.
__global__ __launch_bounds__(256, 2)
void gemm_ws_kernel(const float* __restrict__ Wm,
                    const float* __restrict__ gamma, int iter,
                    float* __restrict__ out_final)
{
    const int K = NMEAS;
    __shared__ float As[8][128];
    __shared__ float Bs[8][128];
    __shared__ float red[16][128];

    float* s_out = (iter == 3) ? out_final : g_s;

    int tid = threadIdx.x;
    int row0 = blockIdx.x * 128, col0 = blockIdx.y * 128;
    int arow = tid >> 1, ac4 = tid & 1;
    int bk = tid >> 5, bc = tid & 31;
    int tm = tid >> 4, tn = tid & 15;

    float acc[8][8];
    #pragma unroll
    for (int i = 0; i < 8; i++)
        #pragma unroll
        for (int j = 0; j < 8; j++) acc[i][j] = 0.0f;

    const float* aptr = Wm + (size_t)(row0 + arow) * K + ac4 * 4;
    int bcol = col0 + bc * 4;
    bool bvalid = (bcol < NB);

    for (int k0 = 0; k0 < K; k0 += 8) {
        float4 av = *(const float4*)(aptr + k0);
        float4 bv = make_float4(0.f, 0.f, 0.f, 0.f);
        if (bvalid) bv = *(const float4*)(g_t + (size_t)(k0 + bk) * NB + bcol);
        As[ac4 * 4 + 0][arow] = av.x;
        As[ac4 * 4 + 1][arow] = av.y;
        As[ac4 * 4 + 2][arow] = av.z;
        As[ac4 * 4 + 3][arow] = av.w;
        *(float4*)&Bs[bk][bc * 4] = bv;
        __syncthreads();
        #pragma unroll
        for (int kk = 0; kk < 8; kk++) {
            float a[8], b[8];
            *(float4*)(a)     = *(const float4*)&As[kk][tm * 8];
            *(float4*)(a + 4) = *(const float4*)&As[kk][tm * 8 + 4];
            *(float4*)(b)     = *(const float4*)&Bs[kk][tn * 8];
            *(float4*)(b + 4) = *(const float4*)&Bs[kk][tn * 8 + 4];
            #pragma unroll
            for (int i = 0; i < 8; i++)
                #pragma unroll
                for (int j = 0; j < 8; j++) acc[i][j] += a[i] * b[j];
        }
        __syncthreads();
    }

    // ---- epilogue: r = s + g*acc ; z = r*coef[col]; softmax over 32-row sections
    float g = gamma[iter];
    int lc = tn * 8;
    int secBase = (tm >> 2) << 2;    // first tm of my 32-row section

    float coefv[8];
    bool cval[8];
    #pragma unroll
    for (int j = 0; j < 8; j++) {
        int col = col0 + lc + j;
        cval[j] = (col < NB);
        coefv[j] = cval[j] ? g_coef[col] : 0.0f;
    }

    // z in-place in acc
    #pragma unroll
    for (int i = 0; i < 8; i++) {
        int row = row0 + tm * 8 + i;
        #pragma unroll
        for (int j = 0; j < 8; j++) {
            int col = col0 + lc + j;
            float sv = 0.0f;
            if (iter != 0 && cval[j]) sv = g_s[(size_t)row * NB + col];
            acc[i][j] = (sv + g * acc[i][j]) * coefv[j];
        }
    }

    // local max over my 8 rows per column
    float lmax[8];
    #pragma unroll
    for (int j = 0; j < 8; j++) {
        float m = acc[0][j];
        #pragma unroll
        for (int i = 1; i < 8; i++) m = fmaxf(m, acc[i][j]);
        lmax[j] = m;
    }
    #pragma unroll
    for (int j = 0; j < 8; j++) red[tm][lc + j] = lmax[j];
    __syncthreads();

    float smax[8];
    #pragma unroll
    for (int j = 0; j < 8; j++) {
        float m = red[secBase + 0][lc + j];
        m = fmaxf(m, red[secBase + 1][lc + j]);
        m = fmaxf(m, red[secBase + 2][lc + j]);
        m = fmaxf(m, red[secBase + 3][lc + j]);
        smax[j] = m;
    }
    __syncthreads();

    // exp and local sums
    float lsum[8];
    #pragma unroll
    for (int j = 0; j < 8; j++) {
        float s = 0.0f;
        #pragma unroll
        for (int i = 0; i < 8; i++) {
            float e = expf(acc[i][j] - smax[j]);
            acc[i][j] = e;
            s += e;
        }
        lsum[j] = s;
    }
    #pragma unroll
    for (int j = 0; j < 8; j++) red[tm][lc + j] = lsum[j];
    __syncthreads();

    float sinv[8];
    #pragma unroll
    for (int j = 0; j < 8; j++) {
        float s = red[secBase + 0][lc + j] + red[secBase + 1][lc + j]
                + red[secBase + 2][lc + j] + red[secBase + 3][lc + j];
        sinv[j] = 1.0f / s;
    }

    #pragma unroll
    for (int i = 0; i < 8; i++) {
        int row = row0 + tm * 8 + i;
        #pragma unroll
        for (int j = 0; j < 8; j++) {
            int col = col0 + lc + j;
            if (cval[j]) s_out[(size_t)row * NB + col] = acc[i][j] * sinv[j];
        }
    }
}

// ---------------- launch --------------------------------------------------
extern "C" void kernel_launch(void* const* d_in, const int* in_sizes, int n_in,
                              void* d_out, int out_size)
{
    const float* x     = (const float*)d_in[0];
    // d_in[1] = s (zeros) -- unused, s0=0 handled by iter==0 path
    const float* noise = (const float*)d_in[2];
    const float* A     = (const float*)d_in[3];
    const float* W     = (const float*)d_in[4];
    const float* gamma = (const float*)d_in[5];
    float* out = (float*)d_out;

    // scalars
    init_scalars_kernel<<<1, 32>>>();
    reduce_sq_kernel<<<512, 256>>>(A, (long)(NMEAS) * NROWS / 4);

    // y = A@x + noise  (also t0 = y)
    dim3 gn(NMEAS / 128, (NB + 127) / 128);   // 40 x 4
    dim3 gw(NROWS / 128, (NB + 127) / 128);   // 128 x 4
    gemm_n_kernel<<<gn, 256>>>(A, x, noise, /*first=*/1, NROWS);

    for (int it = 0; it < MAXITR; it++) {
        zero_colacc_kernel<<<1, 512>>>();
        colsum_kernel<<<NMEAS / 128, 512>>>();
        finalize_kernel<<<1, 512>>>(gamma, it);
        gemm_ws_kernel<<<gw, 256>>>(W, gamma, it, out);
        if (it < MAXITR - 1)
            gemm_n_kernel<<<gn, 256>>>(A, nullptr, nullptr, /*first=*/0, NROWS);
    }
}

// round 4
// speedup vs baseline: 2.5857x; 2.5857x over previous
#include <cuda_runtime.h>
#include <cuda_bf16.h>
#include <cstdint>
#include <math.h>

// ---------------- Problem constants ----------------
#define NROWS 16384      // N
#define NMEAS 5120       // n
#define NB    500        // batch
#define NBP   512        // padded batch
#define MSEC  32
#define SIGMA2f 0.2f
#define SCALEf  3.1622776601683795f
#define MAXITR 4

// Tile config
#define BM 128
#define BN 128
#define BK 32
#define KSPLIT 8
#define KCHUNK (NROWS / KSPLIT)     // 2048

// smem stage: Ah[8K] Al[8K] Bh[8K] Bl[8K]
#define OFF_LO 8192
#define OFF_B  16384
#define STAGE_BYTES 32768
#define DYN_SMEM (2 * STAGE_BYTES)

// ---------------- Scratch (device globals) ----------------
__device__ float  g_xT[(size_t)NBP * NROWS];
__device__ float  g_sT[(size_t)NBP * NROWS];
__device__ float  g_tT[(size_t)NBP * NMEAS];
__device__ float  g_yT[(size_t)NBP * NMEAS];
__device__ float  g_part[(size_t)KSPLIT * NMEAS * NBP];   // split-K partials
__device__ double g_taa;
__device__ float  g_colacc[NBP];
__device__ float  g_coef[NBP];

// ---------------- PTX helpers ----------------
__device__ __forceinline__ uint32_t smem_u32(const void* p){
    uint32_t a;
    asm("{ .reg .u64 t; cvta.to.shared.u64 t, %1; cvt.u32.u64 %0, t; }"
        : "=r"(a) : "l"(p));
    return a;
}
__device__ __forceinline__ void ldsm4(uint32_t& r0, uint32_t& r1, uint32_t& r2,
                                      uint32_t& r3, uint32_t addr){
    asm volatile("ldmatrix.sync.aligned.m8n8.x4.shared.b16 {%0,%1,%2,%3}, [%4];"
                 : "=r"(r0), "=r"(r1), "=r"(r2), "=r"(r3) : "r"(addr));
}
__device__ __forceinline__ void mma16816(float* d, const uint32_t* a, const uint32_t* b){
    asm volatile(
        "mma.sync.aligned.m16n8k16.row.col.f32.bf16.bf16.f32 "
        "{%0,%1,%2,%3}, {%4,%5,%6,%7}, {%8,%9}, {%0,%1,%2,%3};"
        : "+f"(d[0]), "+f"(d[1]), "+f"(d[2]), "+f"(d[3])
        : "r"(a[0]), "r"(a[1]), "r"(a[2]), "r"(a[3]), "r"(b[0]), "r"(b[1]));
}
__device__ __forceinline__ void sts4u(uint32_t a, uint32_t x, uint32_t y,
                                      uint32_t z, uint32_t w){
    asm volatile("st.shared.v4.b32 [%0], {%1,%2,%3,%4};"
                 :: "r"(a), "r"(x), "r"(y), "r"(z), "r"(w) : "memory");
}

// split 8 consecutive floats into 4 packed bf16x2 hi words + 4 lo words
__device__ __forceinline__ void split8(const float* f, uint32_t* hi, uint32_t* lo){
    #pragma unroll
    for (int i = 0; i < 4; i++){
        float x = f[2*i], y = f[2*i+1];
        __nv_bfloat16 hx = __float2bfloat16_rn(x), hy = __float2bfloat16_rn(y);
        float rx = x - __bfloat162float(hx);
        float ry = y - __bfloat162float(hy);
        __nv_bfloat16 lx = __float2bfloat16_rn(rx), ly = __float2bfloat16_rn(ry);
        hi[i] = (uint32_t)__bfloat16_as_ushort(hx) | ((uint32_t)__bfloat16_as_ushort(hy) << 16);
        lo[i] = (uint32_t)__bfloat16_as_ushort(lx) | ((uint32_t)__bfloat16_as_ushort(ly) << 16);
    }
}

// ---------------- bf16 3-split GEMM mainloop ----------------
// acc[4][4][4] += A[128 x S*32] * B[128 x S*32]^T (both K-major, fp32 in gmem)
__device__ __forceinline__ void gemm_loop(
    const float* __restrict__ Arows, const float* __restrict__ Brows,
    size_t strideA, size_t strideB, int S, char* sm, float acc[4][4][4])
{
    const int tid = threadIdx.x, lane = tid & 31, wid = tid >> 5;
    const int wm = wid >> 2, wn = wid & 3;
    const uint32_t smbase = smem_u32(sm);

    // global load pointers: thread covers row=tid>>1, 16 floats at k=(tid&1)*16
    const float* ap = Arows + (size_t)(tid >> 1) * strideA + (tid & 1) * 16;
    const float* bp = Brows + (size_t)(tid >> 1) * strideB + (tid & 1) * 16;

    // STS offsets (same for all 4 tiles; different tile bases)
    const int srow = tid >> 1;
    const int cb = (tid & 1) * 2;
    const int ssw = (srow >> 1) & 3;
    const uint32_t o0 = (uint32_t)(srow * 64 + ((cb    ) ^ ssw) * 16);
    const uint32_t o1 = (uint32_t)(srow * 64 + ((cb + 1) ^ ssw) * 16);

    // LDSM lane addressing
    const int rA = wm * 64 + (lane & 15);
    const int swA = (rA >> 1) & 3;
    const int cA = lane >> 4;                      // 0/1
    const uint32_t ldA = smbase + rA * 64;
    const int rB = wn * 32 + (lane & 7) + ((lane >> 4) & 1) * 8;
    const int swB = (rB >> 1) & 3;
    const int cBc = (lane >> 3) & 1;
    const uint32_t ldB = smbase + rB * 64;

    float4 fa[4], fb[4];
    #pragma unroll
    for (int i = 0; i < 4; i++){
        fa[i] = *(const float4*)(ap + i * 4);
        fb[i] = *(const float4*)(bp + i * 4);
    }

    auto sts_stage = [&](int buf){
        uint32_t base = smbase + buf * STAGE_BYTES;
        uint32_t hi[8], lo[8];
        split8((const float*)fa, hi, lo);
        split8(((const float*)fa) + 8, hi + 4, lo + 4);
        sts4u(base + o0, hi[0], hi[1], hi[2], hi[3]);
        sts4u(base + o1, hi[4], hi[5], hi[6], hi[7]);
        sts4u(base + OFF_LO + o0, lo[0], lo[1], lo[2], lo[3]);
        sts4u(base + OFF_LO + o1, lo[4], lo[5], lo[6], lo[7]);
        split8((const float*)fb, hi, lo);
        split8(((const float*)fb) + 8, hi + 4, lo + 4);
        sts4u(base + OFF_B + o0, hi[0], hi[1], hi[2], hi[3]);
        sts4u(base + OFF_B + o1, hi[4], hi[5], hi[6], hi[7]);
        sts4u(base + OFF_B + OFF_LO + o0, lo[0], lo[1], lo[2], lo[3]);
        sts4u(base + OFF_B + OFF_LO + o1, lo[4], lo[5], lo[6], lo[7]);
    };

    sts_stage(0);
    __syncthreads();

    for (int s = 0; s < S; s++){
        const int buf = s & 1;
        const uint32_t so = buf * STAGE_BYTES;
        if (s + 1 < S){
            const float* a2 = ap + (size_t)(s + 1) * BK;
            const float* b2 = bp + (size_t)(s + 1) * BK;
            #pragma unroll
            for (int i = 0; i < 4; i++){
                fa[i] = *(const float4*)(a2 + i * 4);
                fb[i] = *(const float4*)(b2 + i * 4);
            }
        }
        #pragma unroll
        for (int kk = 0; kk < 2; kk++){
            uint32_t ah[4][4], al[4][4], bh[4][2], bl[4][2];
            const uint32_t aoffk = (uint32_t)(((cA + 2 * kk) ^ swA) * 16);
            const uint32_t boffk = (uint32_t)(((cBc + 2 * kk) ^ swB) * 16);
            #pragma unroll
            for (int mf = 0; mf < 4; mf++){
                uint32_t ad = ldA + so + mf * 1024 + aoffk;
                ldsm4(ah[mf][0], ah[mf][1], ah[mf][2], ah[mf][3], ad);
                ldsm4(al[mf][0], al[mf][1], al[mf][2], al[mf][3], ad + OFF_LO);
            }
            #pragma unroll
            for (int np = 0; np < 2; np++){
                uint32_t bd = ldB + so + OFF_B + np * 1024 + boffk;
                ldsm4(bh[np*2][0], bh[np*2][1], bh[np*2+1][0], bh[np*2+1][1], bd);
                ldsm4(bl[np*2][0], bl[np*2][1], bl[np*2+1][0], bl[np*2+1][1], bd + OFF_LO);
            }
            #pragma unroll
            for (int mf = 0; mf < 4; mf++)
                #pragma unroll
                for (int nf = 0; nf < 4; nf++)
                    mma16816(acc[mf][nf], ah[mf], bh[nf]);
            #pragma unroll
            for (int mf = 0; mf < 4; mf++)
                #pragma unroll
                for (int nf = 0; nf < 4; nf++)
                    mma16816(acc[mf][nf], ah[mf], bl[nf]);
            #pragma unroll
            for (int mf = 0; mf < 4; mf++)
                #pragma unroll
                for (int nf = 0; nf < 4; nf++)
                    mma16816(acc[mf][nf], al[mf], bh[nf]);
        }
        if (s + 1 < S){
            __syncthreads();
            sts_stage(buf ^ 1);
            __syncthreads();
        }
    }
}

// ---------------- GEMM 1 (split-K): partials of A @ X ----------------
__global__ __launch_bounds__(256, 1)
void gemm_t_split_kernel(const float* __restrict__ Am, int first)
{
    extern __shared__ char sm[];
    const int row0 = blockIdx.x * BM, col0 = blockIdx.y * BN, z = blockIdx.z;
    const float* B = first ? g_xT : g_sT;

    float acc[4][4][4];
    #pragma unroll
    for (int i = 0; i < 4; i++)
        #pragma unroll
        for (int j = 0; j < 4; j++)
            #pragma unroll
            for (int k = 0; k < 4; k++) acc[i][j][k] = 0.f;

    gemm_loop(Am + (size_t)row0 * NROWS + (size_t)z * KCHUNK,
              B  + (size_t)col0 * NROWS + (size_t)z * KCHUNK,
              NROWS, NROWS, KCHUNK / BK, sm, acc);

    const int lane = threadIdx.x & 31, wid = threadIdx.x >> 5;
    const int wm = wid >> 2, wn = wid & 3;
    float* P = g_part + (size_t)z * NMEAS * NBP;
    const int r0 = row0 + wm * 64 + (lane >> 2);
    const int c0 = col0 + wn * 32 + (lane & 3) * 2;
    #pragma unroll
    for (int mf = 0; mf < 4; mf++){
        #pragma unroll
        for (int nf = 0; nf < 4; nf++){
            int r = r0 + mf * 16, c = c0 + nf * 8;
            *(float2*)&P[(size_t)r * NBP + c]       = make_float2(acc[mf][nf][0], acc[mf][nf][1]);
            *(float2*)&P[(size_t)(r + 8) * NBP + c] = make_float2(acc[mf][nf][2], acc[mf][nf][3]);
        }
    }
}

// ---------------- reduce partials + t epilogue ----------------
__global__ void reduce_t_kernel(const float* __restrict__ noise, int first)
{
    int idx = blockIdx.x * 256 + threadIdx.x;          // one float4 of columns
    int row = idx / (NBP / 4);
    int col = (idx % (NBP / 4)) * 4;
    float4 sacc = make_float4(0.f, 0.f, 0.f, 0.f);
    #pragma unroll
    for (int z = 0; z < KSPLIT; z++){
        float4 p = *(const float4*)&g_part[(size_t)z * NMEAS * NBP + (size_t)row * NBP + col];
        sacc.x += p.x; sacc.y += p.y; sacc.z += p.z; sacc.w += p.w;
    }
    float d[4] = {sacc.x, sacc.y, sacc.z, sacc.w};
    #pragma unroll
    for (int j = 0; j < 4; j++){
        int c = col + j;
        if (c < NB){
            float v;
            if (first){
                v = noise[(size_t)row * NB + c] + d[j];
                g_yT[(size_t)c * NMEAS + row] = v;
            } else {
                v = g_yT[(size_t)c * NMEAS + row] - d[j];
            }
            g_tT[(size_t)c * NMEAS + row] = v;
        }
    }
}

// ---------------- GEMM 2 + fused per-section softmax ----------------
__global__ __launch_bounds__(256, 1)
void gemm_s_kernel(const float* __restrict__ Wm, const float* __restrict__ gammap,
                   int iter, float* __restrict__ outp)
{
    extern __shared__ char sm[];
    const int row0 = blockIdx.x * BM, col0 = blockIdx.y * BN;

    float acc[4][4][4];
    #pragma unroll
    for (int i = 0; i < 4; i++)
        #pragma unroll
        for (int j = 0; j < 4; j++)
            #pragma unroll
            for (int k = 0; k < 4; k++) acc[i][j][k] = 0.f;

    gemm_loop(Wm + (size_t)row0 * NMEAS, g_tT + (size_t)col0 * NMEAS,
              NMEAS, NMEAS, NMEAS / BK, sm, acc);

    const int lane = threadIdx.x & 31, wid = threadIdx.x >> 5;
    const int wm = wid >> 2, wn = wid & 3;
    const float g = gammap[iter];
    const int r0 = row0 + wm * 64 + (lane >> 2);
    const int ccb = col0 + wn * 32 + (lane & 3) * 2;

    #pragma unroll
    for (int p = 0; p < 2; p++){
        const int rr = r0 + p * 32;
        #pragma unroll
        for (int nf = 0; nf < 4; nf++){
            #pragma unroll
            for (int j = 0; j < 2; j++){
                int col = ccb + nf * 8 + j;
                bool valid = col < NB;
                float cf = valid ? g_coef[col] : 0.f;
                float z0 = acc[2*p  ][nf][j    ] * g;
                float z1 = acc[2*p  ][nf][j + 2] * g;
                float z2 = acc[2*p+1][nf][j    ] * g;
                float z3 = acc[2*p+1][nf][j + 2] * g;
                if (iter > 0 && valid){
                    const float* sp = g_sT + (size_t)col * NROWS;
                    z0 += sp[rr]; z1 += sp[rr + 8]; z2 += sp[rr + 16]; z3 += sp[rr + 24];
                }
                z0 *= cf; z1 *= cf; z2 *= cf; z3 *= cf;
                float m = fmaxf(fmaxf(z0, z1), fmaxf(z2, z3));
                #pragma unroll
                for (int o = 4; o <= 16; o <<= 1)
                    m = fmaxf(m, __shfl_xor_sync(0xffffffffu, m, o));
                float e0 = __expf(z0 - m), e1 = __expf(z1 - m);
                float e2 = __expf(z2 - m), e3 = __expf(z3 - m);
                float su = (e0 + e1) + (e2 + e3);
                #pragma unroll
                for (int o = 4; o <= 16; o <<= 1)
                    su += __shfl_xor_sync(0xffffffffu, su, o);
                float inv = __fdividef(1.f, su);
                if (valid){
                    if (iter == MAXITR - 1){
                        outp[(size_t)rr * NB + col]        = e0 * inv;
                        outp[(size_t)(rr + 8)  * NB + col] = e1 * inv;
                        outp[(size_t)(rr + 16) * NB + col] = e2 * inv;
                        outp[(size_t)(rr + 24) * NB + col] = e3 * inv;
                    } else {
                        float* sp = g_sT + (size_t)col * NROWS;
                        sp[rr]      = e0 * inv;
                        sp[rr + 8]  = e1 * inv;
                        sp[rr + 16] = e2 * inv;
                        sp[rr + 24] = e3 * inv;
                    }
                }
            }
        }
    }
}

// ---------------- small kernels ----------------
__global__ void init_scalars_kernel(){
    if (threadIdx.x == 0) g_taa = 0.0;
}

__global__ void reduce_sq_kernel(const float* __restrict__ a, long n4){
    double acc = 0.0;
    const float4* p = (const float4*)a;
    for (long i = (long)blockIdx.x * blockDim.x + threadIdx.x; i < n4;
         i += (long)gridDim.x * blockDim.x){
        float4 v = p[i];
        acc += (double)v.x*v.x + (double)v.y*v.y + (double)v.z*v.z + (double)v.w*v.w;
    }
    __shared__ double smd[256];
    smd[threadIdx.x] = acc;
    __syncthreads();
    for (int s = 128; s > 0; s >>= 1){
        if (threadIdx.x < s) smd[threadIdx.x] += smd[threadIdx.x + s];
        __syncthreads();
    }
    if (threadIdx.x == 0) atomicAdd(&g_taa, smd[0]);
}

__global__ void transpose_x_kernel(const float* __restrict__ x){
    __shared__ float tile[32][33];
    int k0 = blockIdx.x * 32, n0 = blockIdx.y * 32;
    int tx = threadIdx.x, ty = threadIdx.y;
    #pragma unroll
    for (int i = 0; i < 32; i += 8){
        int k = k0 + ty + i, n = n0 + tx;
        tile[ty + i][tx] = (n < NB) ? x[(size_t)k * NB + n] : 0.f;
    }
    __syncthreads();
    #pragma unroll
    for (int i = 0; i < 32; i += 8){
        int n = n0 + ty + i, k = k0 + tx;
        g_xT[(size_t)n * NROWS + k] = tile[tx][ty + i];
    }
}

__global__ void colsumT_kernel(){
    int c = blockIdx.x;
    const float* p = g_tT + (size_t)c * NMEAS;
    float acc = 0.f;
    for (int k = threadIdx.x; k < NMEAS; k += 256){
        float v = p[k];
        acc = fmaf(v, v, acc);
    }
    #pragma unroll
    for (int o = 16; o; o >>= 1) acc += __shfl_xor_sync(0xffffffffu, acc, o);
    __shared__ float smf[8];
    if ((threadIdx.x & 31) == 0) smf[threadIdx.x >> 5] = acc;
    __syncthreads();
    if (threadIdx.x < 8){
        float a = smf[threadIdx.x];
        #pragma unroll
        for (int o = 4; o; o >>= 1) a += __shfl_xor_sync(0xffu, a, o);
        if (threadIdx.x == 0) g_colacc[c] = a;
    }
}

__global__ void finalize_kernel(const float* __restrict__ gamma, int iter){
    int c = threadIdx.x;
    if (c >= NB) return;
    float taa = (float)g_taa;
    float tww = taa;
    float g = gamma[iter];
    float v2 = (g_colacc[c] - (float)MSEC * SIGMA2f) / taa;
    float tau2 = v2 / (float)NROWS * ((float)NROWS + (g*g - 2.0f*g) * (float)MSEC)
               + g * g * tww * SIGMA2f / (float)NROWS;
    g_coef[c] = SCALEf / tau2;
}

// ---------------- launch ----------------
extern "C" void kernel_launch(void* const* d_in, const int* in_sizes, int n_in,
                              void* d_out, int out_size)
{
    const float* x     = (const float*)d_in[0];
    const float* noise = (const float*)d_in[2];
    const float* A     = (const float*)d_in[3];
    const float* W     = (const float*)d_in[4];
    const float* gamma = (const float*)d_in[5];
    float* out = (float*)d_out;

    cudaFuncSetAttribute((const void*)gemm_t_split_kernel,
                         cudaFuncAttributeMaxDynamicSharedMemorySize, DYN_SMEM);
    cudaFuncSetAttribute((const void*)gemm_s_kernel,
                         cudaFuncAttributeMaxDynamicSharedMemorySize, DYN_SMEM);

    init_scalars_kernel<<<1, 32>>>();
    reduce_sq_kernel<<<512, 256>>>(A, (long)NMEAS * NROWS / 4);
    transpose_x_kernel<<<dim3(NROWS/32, NBP/32), dim3(32, 8)>>>(x);

    // y = A x + noise (t0 = y)
    gemm_t_split_kernel<<<dim3(NMEAS/BM, NBP/BN, KSPLIT), 256, DYN_SMEM>>>(A, 1);
    reduce_t_kernel<<<NMEAS * NBP / 4 / 256, 256>>>(noise, 1);

    for (int it = 0; it < MAXITR; it++){
        colsumT_kernel<<<NB, 256>>>();
        finalize_kernel<<<1, 512>>>(gamma, it);
        gemm_s_kernel<<<dim3(NROWS/BM, NBP/BN), 256, DYN_SMEM>>>(W, gamma, it, out);
        if (it < MAXITR - 1){
            gemm_t_split_kernel<<<dim3(NMEAS/BM, NBP/BN, KSPLIT), 256, DYN_SMEM>>>(A, 0);
            reduce_t_kernel<<<NMEAS * NBP / 4 / 256, 256>>>(noise, 0);
        }
    }
}

// round 5
// speedup vs baseline: 3.7632x; 1.4554x over previous
#include <cuda_runtime.h>
#include <cuda_bf16.h>
#include <cstdint>
#include <math.h>

// ---------------- Problem constants ----------------
#define NROWS 16384      // N
#define NMEAS 5120       // n
#define NB    500        // batch
#define NBP   512        // padded batch
#define MSEC  32
#define SIGMA2f 0.2f
#define SCALEf  3.1622776601683795f
#define MAXITR 4

// Tile config
#define BM 128
#define BN 128
#define BK 32
#define KSPLIT 8
#define KCHUNK (NROWS / KSPLIT)     // 2048

#define STAGES 5
#define STAGE_BYTES 32768          // Ah 8K | Al 8K | Bh 8K | Bl 8K
#define OFF_AL 8192
#define OFF_BH 16384
#define DYN_SMEM (STAGES * STAGE_BYTES)

// ---------------- Scratch (device globals) ----------------
__device__ __nv_bfloat16 g_Ah[(size_t)NMEAS * NROWS];
__device__ __nv_bfloat16 g_Al[(size_t)NMEAS * NROWS];
__device__ __nv_bfloat16 g_Wh[(size_t)NROWS * NMEAS];
__device__ __nv_bfloat16 g_Wl[(size_t)NROWS * NMEAS];
__device__ __nv_bfloat16 g_xTh[(size_t)NBP * NROWS];
__device__ __nv_bfloat16 g_xTl[(size_t)NBP * NROWS];
__device__ __nv_bfloat16 g_sTh[(size_t)NBP * NROWS];
__device__ __nv_bfloat16 g_sTl[(size_t)NBP * NROWS];
__device__ __nv_bfloat16 g_tTh[(size_t)NBP * NMEAS];
__device__ __nv_bfloat16 g_tTl[(size_t)NBP * NMEAS];
__device__ float  g_yT[(size_t)NBP * NMEAS];
__device__ float  g_part[(size_t)KSPLIT * NBP * NMEAS];   // [z][col][row]
__device__ double g_taa;
__device__ float  g_colacc[NBP];
__device__ float  g_coef[NBP];

// ---------------- PTX helpers ----------------
__device__ __forceinline__ uint32_t smem_u32(const void* p){
    uint32_t a;
    asm("{ .reg .u64 t; cvta.to.shared.u64 t, %1; cvt.u32.u64 %0, t; }"
        : "=r"(a) : "l"(p));
    return a;
}
__device__ __forceinline__ void cpasync16(uint32_t dst, const void* src){
    asm volatile("cp.async.cg.shared.global [%0], [%1], 16;"
                 :: "r"(dst), "l"(src) : "memory");
}
#define CP_COMMIT()  asm volatile("cp.async.commit_group;" ::: "memory")
#define CP_WAIT(n)   asm volatile("cp.async.wait_group %0;" :: "n"(n) : "memory")

__device__ __forceinline__ void ldsm4(uint32_t& r0, uint32_t& r1, uint32_t& r2,
                                      uint32_t& r3, uint32_t addr){
    asm volatile("ldmatrix.sync.aligned.m8n8.x4.shared.b16 {%0,%1,%2,%3}, [%4];"
                 : "=r"(r0), "=r"(r1), "=r"(r2), "=r"(r3) : "r"(addr));
}
__device__ __forceinline__ void mma16816(float* d, const uint32_t* a, const uint32_t* b){
    asm volatile(
        "mma.sync.aligned.m16n8k16.row.col.f32.bf16.bf16.f32 "
        "{%0,%1,%2,%3}, {%4,%5,%6,%7}, {%8,%9}, {%0,%1,%2,%3};"
        : "+f"(d[0]), "+f"(d[1]), "+f"(d[2]), "+f"(d[3])
        : "r"(a[0]), "r"(a[1]), "r"(a[2]), "r"(a[3]), "r"(b[0]), "r"(b[1]));
}
__device__ __forceinline__ uint32_t pack_bf(__nv_bfloat16 a, __nv_bfloat16 b){
    return (uint32_t)__bfloat16_as_ushort(a) | ((uint32_t)__bfloat16_as_ushort(b) << 16);
}

// ---------------- bf16 3-split GEMM mainloop (cp.async pipelined) ----------
__device__ __forceinline__ void gemm_loop_bf16(
    const __nv_bfloat16* __restrict__ Ah, const __nv_bfloat16* __restrict__ Al,
    const __nv_bfloat16* __restrict__ Bh, const __nv_bfloat16* __restrict__ Bl,
    int strideA, int strideB, int S, uint32_t smbase, float acc[4][4][4])
{
    const int tid = threadIdx.x, lane = tid & 31, wid = tid >> 5;
    const int wm = wid >> 2, wn = wid & 3;

    // cp.async addressing: thread -> row = tid>>1, two 16B chunks at (tid&1)*2
    const int row = tid >> 1;
    const int cb = (tid & 1) * 2;
    const int sw = (row >> 1) & 3;
    const uint32_t o0 = (uint32_t)(row * 64 + ((cb    ) ^ sw) * 16);
    const uint32_t o1 = (uint32_t)(row * 64 + ((cb + 1) ^ sw) * 16);
    const int koff = (tid & 1) * 16;

    const __nv_bfloat16* aH = Ah + (size_t)row * strideA + koff;
    const __nv_bfloat16* aL = Al + (size_t)row * strideA + koff;
    const __nv_bfloat16* bH = Bh + (size_t)row * strideB + koff;
    const __nv_bfloat16* bL = Bl + (size_t)row * strideB + koff;

    auto issue = [&](int s){
        uint32_t base = smbase + (uint32_t)(s % STAGES) * STAGE_BYTES;
        const __nv_bfloat16* pa = aH + s * BK;
        const __nv_bfloat16* pl = aL + s * BK;
        const __nv_bfloat16* pb = bH + s * BK;
        const __nv_bfloat16* pq = bL + s * BK;
        cpasync16(base + o0, pa);                 cpasync16(base + o1, pa + 8);
        cpasync16(base + OFF_AL + o0, pl);        cpasync16(base + OFF_AL + o1, pl + 8);
        cpasync16(base + OFF_BH + o0, pb);        cpasync16(base + OFF_BH + o1, pb + 8);
        cpasync16(base + OFF_BH + OFF_AL + o0, pq);
        cpasync16(base + OFF_BH + OFF_AL + o1, pq + 8);
    };

    // LDSM lane addressing (same mapping as validated R4 kernel)
    const int rA = wm * 64 + (lane & 15);
    const int swA = (rA >> 1) & 3;
    const int cA = lane >> 4;
    const uint32_t ldA = smbase + rA * 64;
    const int rB = wn * 32 + (lane & 7) + ((lane >> 4) & 1) * 8;
    const int swB = (rB >> 1) & 3;
    const int cBc = (lane >> 3) & 1;
    const uint32_t ldB = smbase + rB * 64;

    #pragma unroll
    for (int p = 0; p < STAGES - 1; p++){
        issue(p);
        CP_COMMIT();
    }

    for (int s = 0; s < S; s++){
        CP_WAIT(STAGES - 2);
        __syncthreads();
        const uint32_t so = (uint32_t)(s % STAGES) * STAGE_BYTES;
        #pragma unroll
        for (int kk = 0; kk < 2; kk++){
            uint32_t ah[4][4], al[4][4], bh[4][2], bl[4][2];
            const uint32_t aoffk = (uint32_t)(((cA + 2 * kk) ^ swA) * 16);
            const uint32_t boffk = (uint32_t)(((cBc + 2 * kk) ^ swB) * 16);
            #pragma unroll
            for (int mf = 0; mf < 4; mf++){
                uint32_t ad = ldA + so + mf * 1024 + aoffk;
                ldsm4(ah[mf][0], ah[mf][1], ah[mf][2], ah[mf][3], ad);
                ldsm4(al[mf][0], al[mf][1], al[mf][2], al[mf][3], ad + OFF_AL);
            }
            #pragma unroll
            for (int np = 0; np < 2; np++){
                uint32_t bd = ldB + so + OFF_BH + np * 1024 + boffk;
                ldsm4(bh[np*2][0], bh[np*2][1], bh[np*2+1][0], bh[np*2+1][1], bd);
                ldsm4(bl[np*2][0], bl[np*2][1], bl[np*2+1][0], bl[np*2+1][1], bd + OFF_AL);
            }
            #pragma unroll
            for (int mf = 0; mf < 4; mf++)
                #pragma unroll
                for (int nf = 0; nf < 4; nf++)
                    mma16816(acc[mf][nf], ah[mf], bh[nf]);
            #pragma unroll
            for (int mf = 0; mf < 4; mf++)
                #pragma unroll
                for (int nf = 0; nf < 4; nf++)
                    mma16816(acc[mf][nf], ah[mf], bl[nf]);
            #pragma unroll
            for (int mf = 0; mf < 4; mf++)
                #pragma unroll
                for (int nf = 0; nf < 4; nf++)
                    mma16816(acc[mf][nf], al[mf], bh[nf]);
        }
        int nx = s + STAGES - 1;
        if (nx < S) issue(nx);
        CP_COMMIT();
    }
}

#define ZERO_ACC(acc)                                         \
    float acc[4][4][4];                                       \
    _Pragma("unroll")                                         \
    for (int i = 0; i < 4; i++)                               \
        _Pragma("unroll")                                     \
        for (int j = 0; j < 4; j++)                           \
            _Pragma("unroll")                                 \
            for (int k = 0; k < 4; k++) acc[i][j][k] = 0.f;

// ---------------- GEMM 1 (split-K): partials of A @ X -> g_part[z][c][r] ---
__global__ __launch_bounds__(256, 1)
void gemm_t_split_kernel(int first)
{
    extern __shared__ char sm[];
    const int row0 = blockIdx.x * BM, col0 = blockIdx.y * BN, z = blockIdx.z;
    const __nv_bfloat16* Bh = (first ? g_xTh : g_sTh) + (size_t)col0 * NROWS + (size_t)z * KCHUNK;
    const __nv_bfloat16* Bl = (first ? g_xTl : g_sTl) + (size_t)col0 * NROWS + (size_t)z * KCHUNK;

    ZERO_ACC(acc);
    gemm_loop_bf16(g_Ah + (size_t)row0 * NROWS + (size_t)z * KCHUNK,
                   g_Al + (size_t)row0 * NROWS + (size_t)z * KCHUNK,
                   Bh, Bl, NROWS, NROWS, KCHUNK / BK, smem_u32(sm), acc);

    const int lane = threadIdx.x & 31, wid = threadIdx.x >> 5;
    const int wm = wid >> 2, wn = wid & 3;
    const int r0 = row0 + wm * 64 + (lane >> 2);
    const int c0 = col0 + wn * 32 + (lane & 3) * 2;
    float* P = g_part + (size_t)z * NBP * NMEAS;
    #pragma unroll
    for (int mf = 0; mf < 4; mf++){
        #pragma unroll
        for (int nf = 0; nf < 4; nf++){
            int r = r0 + mf * 16, c = c0 + nf * 8;
            P[(size_t)c * NMEAS + r]           = acc[mf][nf][0];
            P[(size_t)(c + 1) * NMEAS + r]     = acc[mf][nf][1];
            P[(size_t)c * NMEAS + r + 8]       = acc[mf][nf][2];
            P[(size_t)(c + 1) * NMEAS + r + 8] = acc[mf][nf][3];
        }
    }
}

// ---------------- reduce partials + t epilogue (writes tTh/tTl) ------------
__global__ void reduce_t_kernel(const float* __restrict__ noise, int first)
{
    const int c = blockIdx.y;
    const int row = blockIdx.x * 256 + threadIdx.x;
    float a = 0.f;
    #pragma unroll
    for (int z = 0; z < KSPLIT; z++)
        a += g_part[((size_t)z * NBP + c) * NMEAS + row];
    float v;
    if (first){
        v = noise[(size_t)row * NB + c] + a;
        g_yT[(size_t)c * NMEAS + row] = v;
    } else {
        v = g_yT[(size_t)c * NMEAS + row] - a;
    }
    __nv_bfloat16 h = __float2bfloat16_rn(v);
    g_tTh[(size_t)c * NMEAS + row] = h;
    g_tTl[(size_t)c * NMEAS + row] = __float2bfloat16_rn(v - __bfloat162float(h));
}

// ---------------- GEMM 2 + fused per-section softmax -----------------------
__global__ __launch_bounds__(256, 1)
void gemm_s_kernel(const float* __restrict__ gammap, int iter, float* __restrict__ outp)
{
    extern __shared__ char sm[];
    const int row0 = blockIdx.x * BM, col0 = blockIdx.y * BN;

    ZERO_ACC(acc);
    gemm_loop_bf16(g_Wh + (size_t)row0 * NMEAS, g_Wl + (size_t)row0 * NMEAS,
                   g_tTh + (size_t)col0 * NMEAS, g_tTl + (size_t)col0 * NMEAS,
                   NMEAS, NMEAS, NMEAS / BK, smem_u32(sm), acc);

    const int lane = threadIdx.x & 31, wid = threadIdx.x >> 5;
    const int wm = wid >> 2, wn = wid & 3;
    const float g = gammap[iter];
    const int r0 = row0 + wm * 64 + (lane >> 2);
    const int ccb = col0 + wn * 32 + (lane & 3) * 2;

    #pragma unroll
    for (int p = 0; p < 2; p++){
        const int rr = r0 + p * 32;
        #pragma unroll
        for (int nf = 0; nf < 4; nf++){
            #pragma unroll
            for (int j = 0; j < 2; j++){
                int col = ccb + nf * 8 + j;
                bool valid = col < NB;
                float cf = valid ? g_coef[col] : 0.f;
                float z0 = acc[2*p  ][nf][j    ] * g;
                float z1 = acc[2*p  ][nf][j + 2] * g;
                float z2 = acc[2*p+1][nf][j    ] * g;
                float z3 = acc[2*p+1][nf][j + 2] * g;
                if (iter > 0 && valid){
                    const __nv_bfloat16* sh = g_sTh + (size_t)col * NROWS;
                    const __nv_bfloat16* sl = g_sTl + (size_t)col * NROWS;
                    z0 += __bfloat162float(sh[rr])      + __bfloat162float(sl[rr]);
                    z1 += __bfloat162float(sh[rr + 8])  + __bfloat162float(sl[rr + 8]);
                    z2 += __bfloat162float(sh[rr + 16]) + __bfloat162float(sl[rr + 16]);
                    z3 += __bfloat162float(sh[rr + 24]) + __bfloat162float(sl[rr + 24]);
                }
                z0 *= cf; z1 *= cf; z2 *= cf; z3 *= cf;
                float m = fmaxf(fmaxf(z0, z1), fmaxf(z2, z3));
                #pragma unroll
                for (int o = 4; o <= 16; o <<= 1)
                    m = fmaxf(m, __shfl_xor_sync(0xffffffffu, m, o));
                float e0 = __expf(z0 - m), e1 = __expf(z1 - m);
                float e2 = __expf(z2 - m), e3 = __expf(z3 - m);
                float su = (e0 + e1) + (e2 + e3);
                #pragma unroll
                for (int o = 4; o <= 16; o <<= 1)
                    su += __shfl_xor_sync(0xffffffffu, su, o);
                float inv = __fdividef(1.f, su);
                if (valid){
                    float v0 = e0 * inv, v1 = e1 * inv, v2 = e2 * inv, v3 = e3 * inv;
                    if (iter == MAXITR - 1){
                        outp[(size_t)rr * NB + col]        = v0;
                        outp[(size_t)(rr + 8)  * NB + col] = v1;
                        outp[(size_t)(rr + 16) * NB + col] = v2;
                        outp[(size_t)(rr + 24) * NB + col] = v3;
                    } else {
                        __nv_bfloat16* sh = g_sTh + (size_t)col * NROWS;
                        __nv_bfloat16* sl = g_sTl + (size_t)col * NROWS;
                        __nv_bfloat16 h0 = __float2bfloat16_rn(v0);
                        __nv_bfloat16 h1 = __float2bfloat16_rn(v1);
                        __nv_bfloat16 h2 = __float2bfloat16_rn(v2);
                        __nv_bfloat16 h3 = __float2bfloat16_rn(v3);
                        sh[rr]      = h0; sl[rr]      = __float2bfloat16_rn(v0 - __bfloat162float(h0));
                        sh[rr + 8]  = h1; sl[rr + 8]  = __float2bfloat16_rn(v1 - __bfloat162float(h1));
                        sh[rr + 16] = h2; sl[rr + 16] = __float2bfloat16_rn(v2 - __bfloat162float(h2));
                        sh[rr + 24] = h3; sl[rr + 24] = __float2bfloat16_rn(v3 - __bfloat162float(h3));
                    }
                }
            }
        }
    }
}

// ---------------- conversion / small kernels --------------------------------
__global__ void init_scalars_kernel(){
    if (threadIdx.x == 0) g_taa = 0.0;
}

// split fp32 -> bf16 hi/lo; optionally accumulate sum of squares (taa)
__global__ void conv_split_kernel(const float* __restrict__ src,
                                  __nv_bfloat16* __restrict__ hi,
                                  __nv_bfloat16* __restrict__ lo,
                                  long n4, int do_taa)
{
    double t = 0.0;
    const float4* s4 = (const float4*)src;
    uint2* h2 = (uint2*)hi;
    uint2* l2 = (uint2*)lo;
    for (long i = (long)blockIdx.x * blockDim.x + threadIdx.x; i < n4;
         i += (long)gridDim.x * blockDim.x){
        float4 v = s4[i];
        __nv_bfloat16 hx = __float2bfloat16_rn(v.x), hy = __float2bfloat16_rn(v.y);
        __nv_bfloat16 hz = __float2bfloat16_rn(v.z), hw = __float2bfloat16_rn(v.w);
        __nv_bfloat16 lx = __float2bfloat16_rn(v.x - __bfloat162float(hx));
        __nv_bfloat16 ly = __float2bfloat16_rn(v.y - __bfloat162float(hy));
        __nv_bfloat16 lz = __float2bfloat16_rn(v.z - __bfloat162float(hz));
        __nv_bfloat16 lw = __float2bfloat16_rn(v.w - __bfloat162float(hw));
        h2[i] = make_uint2(pack_bf(hx, hy), pack_bf(hz, hw));
        l2[i] = make_uint2(pack_bf(lx, ly), pack_bf(lz, lw));
        if (do_taa)
            t += (double)v.x*v.x + (double)v.y*v.y + (double)v.z*v.z + (double)v.w*v.w;
    }
    if (do_taa){
        __shared__ double smd[256];
        smd[threadIdx.x] = t;
        __syncthreads();
        for (int s = 128; s > 0; s >>= 1){
            if (threadIdx.x < s) smd[threadIdx.x] += smd[threadIdx.x + s];
            __syncthreads();
        }
        if (threadIdx.x == 0) atomicAdd(&g_taa, smd[0]);
    }
}

__global__ void transpose_x_kernel(const float* __restrict__ x){
    __shared__ float tile[32][33];
    int k0 = blockIdx.x * 32, n0 = blockIdx.y * 32;
    int tx = threadIdx.x, ty = threadIdx.y;
    #pragma unroll
    for (int i = 0; i < 32; i += 8){
        int k = k0 + ty + i, n = n0 + tx;
        tile[ty + i][tx] = (n < NB) ? x[(size_t)k * NB + n] : 0.f;
    }
    __syncthreads();
    #pragma unroll
    for (int i = 0; i < 32; i += 8){
        int n = n0 + ty + i, k = k0 + tx;
        float v = tile[tx][ty + i];
        __nv_bfloat16 h = __float2bfloat16_rn(v);
        g_xTh[(size_t)n * NROWS + k] = h;
        g_xTl[(size_t)n * NROWS + k] = __float2bfloat16_rn(v - __bfloat162float(h));
    }
}

__global__ void colsumT_kernel(){
    int c = blockIdx.x;
    const __nv_bfloat16* ph = g_tTh + (size_t)c * NMEAS;
    const __nv_bfloat16* pl = g_tTl + (size_t)c * NMEAS;
    float acc = 0.f;
    for (int k = threadIdx.x; k < NMEAS; k += 256){
        float v = __bfloat162float(ph[k]) + __bfloat162float(pl[k]);
        acc = fmaf(v, v, acc);
    }
    #pragma unroll
    for (int o = 16; o; o >>= 1) acc += __shfl_xor_sync(0xffffffffu, acc, o);
    __shared__ float smf[8];
    if ((threadIdx.x & 31) == 0) smf[threadIdx.x >> 5] = acc;
    __syncthreads();
    if (threadIdx.x < 8){
        float a = smf[threadIdx.x];
        #pragma unroll
        for (int o = 4; o; o >>= 1) a += __shfl_xor_sync(0xffu, a, o);
        if (threadIdx.x == 0) g_colacc[c] = a;
    }
}

__global__ void finalize_kernel(const float* __restrict__ gamma, int iter){
    int c = threadIdx.x;
    if (c >= NB) return;
    float taa = (float)g_taa;
    float tww = taa;
    float g = gamma[iter];
    float v2 = (g_colacc[c] - (float)MSEC * SIGMA2f) / taa;
    float tau2 = v2 / (float)NROWS * ((float)NROWS + (g*g - 2.0f*g) * (float)MSEC)
               + g * g * tww * SIGMA2f / (float)NROWS;
    g_coef[c] = SCALEf / tau2;
}

// ---------------- launch ----------------------------------------------------
extern "C" void kernel_launch(void* const* d_in, const int* in_sizes, int n_in,
                              void* d_out, int out_size)
{
    const float* x     = (const float*)d_in[0];
    const float* noise = (const float*)d_in[2];
    const float* A     = (const float*)d_in[3];
    const float* W     = (const float*)d_in[4];
    const float* gamma = (const float*)d_in[5];
    float* out = (float*)d_out;

    cudaFuncSetAttribute((const void*)gemm_t_split_kernel,
                         cudaFuncAttributeMaxDynamicSharedMemorySize, DYN_SMEM);
    cudaFuncSetAttribute((const void*)gemm_s_kernel,
                         cudaFuncAttributeMaxDynamicSharedMemorySize, DYN_SMEM);

    __nv_bfloat16 *dAh, *dAl, *dWh, *dWl;
    cudaGetSymbolAddress((void**)&dAh, g_Ah);
    cudaGetSymbolAddress((void**)&dAl, g_Al);
    cudaGetSymbolAddress((void**)&dWh, g_Wh);
    cudaGetSymbolAddress((void**)&dWl, g_Wl);

    const long n4 = (long)NMEAS * NROWS / 4;

    init_scalars_kernel<<<1, 32>>>();
    conv_split_kernel<<<2048, 256>>>(A, dAh, dAl, n4, 1);   // also computes taa
    conv_split_kernel<<<2048, 256>>>(W, dWh, dWl, n4, 0);
    transpose_x_kernel<<<dim3(NROWS/32, NBP/32), dim3(32, 8)>>>(x);

    // y = A x + noise (t0 = y)
    gemm_t_split_kernel<<<dim3(NMEAS/BM, NBP/BN, KSPLIT), 256, DYN_SMEM>>>(1);
    reduce_t_kernel<<<dim3(NMEAS/256, NB), 256>>>(noise, 1);

    for (int it = 0; it < MAXITR; it++){
        colsumT_kernel<<<NB, 256>>>();
        finalize_kernel<<<1, 512>>>(gamma, it);
        gemm_s_kernel<<<dim3(NROWS/BM, NBP/BN), 256, DYN_SMEM>>>(gamma, it, out);
        if (it < MAXITR - 1){
            gemm_t_split_kernel<<<dim3(NMEAS/BM, NBP/BN, KSPLIT), 256, DYN_SMEM>>>(0);
            reduce_t_kernel<<<dim3(NMEAS/256, NB), 256>>>(noise, 0);
        }
    }
}

// round 6
// speedup vs baseline: 5.0200x; 1.3340x over previous
#include <cuda_runtime.h>
#include <cuda_fp16.h>
#include <cstdint>
#include <math.h>

// ---------------- Problem constants ----------------
#define NROWS 16384      // N
#define NMEAS 5120       // n
#define NB    500        // batch
#define NBP   512        // padded batch
#define MSEC  32
#define SIGMA2f 0.2f
#define SCALEf  3.1622776601683795f
#define MAXITR 4

// Tile config
#define BM 128
#define BN 128
#define BK 32
#define KSPLIT 8
#define KCHUNK (NROWS / KSPLIT)     // 2048

#define STAGES 6
#define STAGE_BYTES 24576          // A 8K | Bh 8K | Bl 8K
#define OFF_BH 8192
#define OFF_BL 16384
#define DYN_SMEM (STAGES * STAGE_BYTES)

// ---------------- Scratch (device globals) ----------------
__device__ __half g_A16[(size_t)NMEAS * NROWS];     // A single fp16
__device__ __half g_W16[(size_t)NROWS * NMEAS];     // W single fp16
__device__ __half g_xTh[(size_t)NBP * NROWS];
__device__ __half g_xTl[(size_t)NBP * NROWS];
__device__ __half g_sTh[(size_t)NBP * NROWS];
__device__ __half g_sTl[(size_t)NBP * NROWS];
__device__ __half g_tTh[(size_t)NBP * NMEAS];
__device__ __half g_tTl[(size_t)NBP * NMEAS];
__device__ float  g_yT[(size_t)NBP * NMEAS];
__device__ float  g_part[(size_t)KSPLIT * NBP * NMEAS];   // [z][col][row]
__device__ double g_taa;
__device__ float  g_colacc[NBP];
__device__ float  g_coef[NBP];

// ---------------- PTX helpers ----------------
__device__ __forceinline__ uint32_t smem_u32(const void* p){
    uint32_t a;
    asm("{ .reg .u64 t; cvta.to.shared.u64 t, %1; cvt.u32.u64 %0, t; }"
        : "=r"(a) : "l"(p));
    return a;
}
__device__ __forceinline__ void cpasync16(uint32_t dst, const void* src){
    asm volatile("cp.async.cg.shared.global [%0], [%1], 16;"
                 :: "r"(dst), "l"(src) : "memory");
}
#define CP_COMMIT()  asm volatile("cp.async.commit_group;" ::: "memory")
#define CP_WAIT(n)   asm volatile("cp.async.wait_group %0;" :: "n"(n) : "memory")

__device__ __forceinline__ void ldsm4(uint32_t& r0, uint32_t& r1, uint32_t& r2,
                                      uint32_t& r3, uint32_t addr){
    asm volatile("ldmatrix.sync.aligned.m8n8.x4.shared.b16 {%0,%1,%2,%3}, [%4];"
                 : "=r"(r0), "=r"(r1), "=r"(r2), "=r"(r3) : "r"(addr));
}
__device__ __forceinline__ void mma16816(float* d, const uint32_t* a, const uint32_t* b){
    asm volatile(
        "mma.sync.aligned.m16n8k16.row.col.f32.f16.f16.f32 "
        "{%0,%1,%2,%3}, {%4,%5,%6,%7}, {%8,%9}, {%0,%1,%2,%3};"
        : "+f"(d[0]), "+f"(d[1]), "+f"(d[2]), "+f"(d[3])
        : "r"(a[0]), "r"(a[1]), "r"(a[2]), "r"(a[3]), "r"(b[0]), "r"(b[1]));
}
__device__ __forceinline__ uint32_t pack_h(__half a, __half b){
    return (uint32_t)__half_as_ushort(a) | ((uint32_t)__half_as_ushort(b) << 16);
}
__device__ __forceinline__ void split_h(float v, __half& hi, __half& lo){
    hi = __float2half_rn(v);
    lo = __float2half_rn(v - __half2float(hi));
}

// ---------------- fp16 2-term GEMM mainloop (cp.async pipelined) -----------
// acc += A_fp16[128 x K] * (Bh + Bl)[128 x K]^T
__device__ __forceinline__ void gemm_loop_f16(
    const __half* __restrict__ Am,
    const __half* __restrict__ Bh, const __half* __restrict__ Bl,
    int strideA, int strideB, int S, uint32_t smbase, float acc[4][4][4])
{
    const int tid = threadIdx.x, lane = tid & 31, wid = tid >> 5;
    const int wm = wid >> 2, wn = wid & 3;

    // cp.async addressing: row = tid>>1, two 16B chunks at (tid&1)*2
    const int row = tid >> 1;
    const int cb = (tid & 1) * 2;
    const int sw = (row >> 1) & 3;
    const uint32_t o0 = (uint32_t)(row * 64 + ((cb    ) ^ sw) * 16);
    const uint32_t o1 = (uint32_t)(row * 64 + ((cb + 1) ^ sw) * 16);
    const int koff = (tid & 1) * 16;

    const __half* aP = Am + (size_t)row * strideA + koff;
    const __half* bH = Bh + (size_t)row * strideB + koff;
    const __half* bL = Bl + (size_t)row * strideB + koff;

    auto issue = [&](int s){
        uint32_t base = smbase + (uint32_t)(s % STAGES) * STAGE_BYTES;
        const __half* pa = aP + s * BK;
        const __half* pb = bH + s * BK;
        const __half* pq = bL + s * BK;
        cpasync16(base + o0, pa);                 cpasync16(base + o1, pa + 8);
        cpasync16(base + OFF_BH + o0, pb);        cpasync16(base + OFF_BH + o1, pb + 8);
        cpasync16(base + OFF_BL + o0, pq);        cpasync16(base + OFF_BL + o1, pq + 8);
    };

    // LDSM lane addressing (validated mapping)
    const int rA = wm * 64 + (lane & 15);
    const int swA = (rA >> 1) & 3;
    const int cA = lane >> 4;
    const uint32_t ldA = smbase + rA * 64;
    const int rB = wn * 32 + (lane & 7) + ((lane >> 4) & 1) * 8;
    const int swB = (rB >> 1) & 3;
    const int cBc = (lane >> 3) & 1;
    const uint32_t ldB = smbase + rB * 64;

    #pragma unroll
    for (int p = 0; p < STAGES - 1; p++){
        issue(p);
        CP_COMMIT();
    }

    for (int s = 0; s < S; s++){
        CP_WAIT(STAGES - 2);
        __syncthreads();
        const uint32_t so = (uint32_t)(s % STAGES) * STAGE_BYTES;
        #pragma unroll
        for (int kk = 0; kk < 2; kk++){
            uint32_t ar[4][4], bh[4][2], bl[4][2];
            const uint32_t aoffk = (uint32_t)(((cA + 2 * kk) ^ swA) * 16);
            const uint32_t boffk = (uint32_t)(((cBc + 2 * kk) ^ swB) * 16);
            #pragma unroll
            for (int mf = 0; mf < 4; mf++){
                uint32_t ad = ldA + so + mf * 1024 + aoffk;
                ldsm4(ar[mf][0], ar[mf][1], ar[mf][2], ar[mf][3], ad);
            }
            #pragma unroll
            for (int np = 0; np < 2; np++){
                uint32_t bd = ldB + so + OFF_BH + np * 1024 + boffk;
                ldsm4(bh[np*2][0], bh[np*2][1], bh[np*2+1][0], bh[np*2+1][1], bd);
                ldsm4(bl[np*2][0], bl[np*2][1], bl[np*2+1][0], bl[np*2+1][1], bd + 8192);
            }
            #pragma unroll
            for (int mf = 0; mf < 4; mf++)
                #pragma unroll
                for (int nf = 0; nf < 4; nf++)
                    mma16816(acc[mf][nf], ar[mf], bh[nf]);
            #pragma unroll
            for (int mf = 0; mf < 4; mf++)
                #pragma unroll
                for (int nf = 0; nf < 4; nf++)
                    mma16816(acc[mf][nf], ar[mf], bl[nf]);
        }
        int nx = s + STAGES - 1;
        if (nx < S) issue(nx);
        CP_COMMIT();
    }
}

#define ZERO_ACC(acc)                                         \
    float acc[4][4][4];                                       \
    _Pragma("unroll")                                         \
    for (int i = 0; i < 4; i++)                               \
        _Pragma("unroll")                                     \
        for (int j = 0; j < 4; j++)                           \
            _Pragma("unroll")                                 \
            for (int k = 0; k < 4; k++) acc[i][j][k] = 0.f;

// ---------------- GEMM 1 (split-K): partials of A @ X -> g_part[z][c][r] ---
__global__ __launch_bounds__(256, 1)
void gemm_t_split_kernel(int first)
{
    extern __shared__ char sm[];
    const int row0 = blockIdx.x * BM, col0 = blockIdx.y * BN, z = blockIdx.z;
    const __half* Bh = (first ? g_xTh : g_sTh) + (size_t)col0 * NROWS + (size_t)z * KCHUNK;
    const __half* Bl = (first ? g_xTl : g_sTl) + (size_t)col0 * NROWS + (size_t)z * KCHUNK;

    ZERO_ACC(acc);
    gemm_loop_f16(g_A16 + (size_t)row0 * NROWS + (size_t)z * KCHUNK,
                  Bh, Bl, NROWS, NROWS, KCHUNK / BK, smem_u32(sm), acc);

    const int lane = threadIdx.x & 31, wid = threadIdx.x >> 5;
    const int wm = wid >> 2, wn = wid & 3;
    const int r0 = row0 + wm * 64 + (lane >> 2);
    const int c0 = col0 + wn * 32 + (lane & 3) * 2;
    float* P = g_part + (size_t)z * NBP * NMEAS;
    #pragma unroll
    for (int mf = 0; mf < 4; mf++){
        #pragma unroll
        for (int nf = 0; nf < 4; nf++){
            int r = r0 + mf * 16, c = c0 + nf * 8;
            P[(size_t)c * NMEAS + r]           = acc[mf][nf][0];
            P[(size_t)(c + 1) * NMEAS + r]     = acc[mf][nf][1];
            P[(size_t)c * NMEAS + r + 8]       = acc[mf][nf][2];
            P[(size_t)(c + 1) * NMEAS + r + 8] = acc[mf][nf][3];
        }
    }
}

// ---------------- reduce partials + t epilogue (writes tTh/tTl) ------------
__global__ void reduce_t_kernel(const float* __restrict__ noise, int first)
{
    const int c = blockIdx.y;
    const int row = blockIdx.x * 256 + threadIdx.x;
    float a = 0.f;
    #pragma unroll
    for (int z = 0; z < KSPLIT; z++)
        a += g_part[((size_t)z * NBP + c) * NMEAS + row];
    float v;
    if (first){
        v = noise[(size_t)row * NB + c] + a;
        g_yT[(size_t)c * NMEAS + row] = v;
    } else {
        v = g_yT[(size_t)c * NMEAS + row] - a;
    }
    __half h, l;
    split_h(v, h, l);
    g_tTh[(size_t)c * NMEAS + row] = h;
    g_tTl[(size_t)c * NMEAS + row] = l;
}

// ---------------- GEMM 2 + fused per-section softmax -----------------------
__global__ __launch_bounds__(256, 1)
void gemm_s_kernel(const float* __restrict__ gammap, int iter, float* __restrict__ outp)
{
    extern __shared__ char sm[];
    const int row0 = blockIdx.x * BM, col0 = blockIdx.y * BN;

    ZERO_ACC(acc);
    gemm_loop_f16(g_W16 + (size_t)row0 * NMEAS,
                  g_tTh + (size_t)col0 * NMEAS, g_tTl + (size_t)col0 * NMEAS,
                  NMEAS, NMEAS, NMEAS / BK, smem_u32(sm), acc);

    const int lane = threadIdx.x & 31, wid = threadIdx.x >> 5;
    const int wm = wid >> 2, wn = wid & 3;
    const float g = gammap[iter];
    const int r0 = row0 + wm * 64 + (lane >> 2);
    const int ccb = col0 + wn * 32 + (lane & 3) * 2;

    #pragma unroll
    for (int p = 0; p < 2; p++){
        const int rr = r0 + p * 32;
        #pragma unroll
        for (int nf = 0; nf < 4; nf++){
            #pragma unroll
            for (int j = 0; j < 2; j++){
                int col = ccb + nf * 8 + j;
                bool valid = col < NB;
                float cf = valid ? g_coef[col] : 0.f;
                float z0 = acc[2*p  ][nf][j    ] * g;
                float z1 = acc[2*p  ][nf][j + 2] * g;
                float z2 = acc[2*p+1][nf][j    ] * g;
                float z3 = acc[2*p+1][nf][j + 2] * g;
                if (iter > 0 && valid){
                    const __half* sh = g_sTh + (size_t)col * NROWS;
                    const __half* sl = g_sTl + (size_t)col * NROWS;
                    z0 += __half2float(sh[rr])      + __half2float(sl[rr]);
                    z1 += __half2float(sh[rr + 8])  + __half2float(sl[rr + 8]);
                    z2 += __half2float(sh[rr + 16]) + __half2float(sl[rr + 16]);
                    z3 += __half2float(sh[rr + 24]) + __half2float(sl[rr + 24]);
                }
                z0 *= cf; z1 *= cf; z2 *= cf; z3 *= cf;
                float m = fmaxf(fmaxf(z0, z1), fmaxf(z2, z3));
                #pragma unroll
                for (int o = 4; o <= 16; o <<= 1)
                    m = fmaxf(m, __shfl_xor_sync(0xffffffffu, m, o));
                float e0 = __expf(z0 - m), e1 = __expf(z1 - m);
                float e2 = __expf(z2 - m), e3 = __expf(z3 - m);
                float su = (e0 + e1) + (e2 + e3);
                #pragma unroll
                for (int o = 4; o <= 16; o <<= 1)
                    su += __shfl_xor_sync(0xffffffffu, su, o);
                float inv = __fdividef(1.f, su);
                if (valid){
                    float v0 = e0 * inv, v1 = e1 * inv, v2 = e2 * inv, v3 = e3 * inv;
                    if (iter == MAXITR - 1){
                        outp[(size_t)rr * NB + col]        = v0;
                        outp[(size_t)(rr + 8)  * NB + col] = v1;
                        outp[(size_t)(rr + 16) * NB + col] = v2;
                        outp[(size_t)(rr + 24) * NB + col] = v3;
                    } else {
                        __half* sh = g_sTh + (size_t)col * NROWS;
                        __half* sl = g_sTl + (size_t)col * NROWS;
                        __half h, l;
                        split_h(v0, h, l); sh[rr]      = h; sl[rr]      = l;
                        split_h(v1, h, l); sh[rr + 8]  = h; sl[rr + 8]  = l;
                        split_h(v2, h, l); sh[rr + 16] = h; sl[rr + 16] = l;
                        split_h(v3, h, l); sh[rr + 24] = h; sl[rr + 24] = l;
                    }
                }
            }
        }
    }
}

// ---------------- conversion / small kernels --------------------------------
__global__ void init_scalars_kernel(){
    if (threadIdx.x == 0) g_taa = 0.0;
}

// fp32 -> single fp16; optionally accumulate sum of squares (taa)
__global__ void conv_f16_kernel(const float* __restrict__ src,
                                __half* __restrict__ dst, long n4, int do_taa)
{
    double t = 0.0;
    const float4* s4 = (const float4*)src;
    uint2* d2 = (uint2*)dst;
    for (long i = (long)blockIdx.x * blockDim.x + threadIdx.x; i < n4;
         i += (long)gridDim.x * blockDim.x){
        float4 v = s4[i];
        d2[i] = make_uint2(pack_h(__float2half_rn(v.x), __float2half_rn(v.y)),
                           pack_h(__float2half_rn(v.z), __float2half_rn(v.w)));
        if (do_taa)
            t += (double)v.x*v.x + (double)v.y*v.y + (double)v.z*v.z + (double)v.w*v.w;
    }
    if (do_taa){
        __shared__ double smd[256];
        smd[threadIdx.x] = t;
        __syncthreads();
        for (int s = 128; s > 0; s >>= 1){
            if (threadIdx.x < s) smd[threadIdx.x] += smd[threadIdx.x + s];
            __syncthreads();
        }
        if (threadIdx.x == 0) atomicAdd(&g_taa, smd[0]);
    }
}

__global__ void transpose_x_kernel(const float* __restrict__ x){
    __shared__ float tile[32][33];
    int k0 = blockIdx.x * 32, n0 = blockIdx.y * 32;
    int tx = threadIdx.x, ty = threadIdx.y;
    #pragma unroll
    for (int i = 0; i < 32; i += 8){
        int k = k0 + ty + i, n = n0 + tx;
        tile[ty + i][tx] = (n < NB) ? x[(size_t)k * NB + n] : 0.f;
    }
    __syncthreads();
    #pragma unroll
    for (int i = 0; i < 32; i += 8){
        int n = n0 + ty + i, k = k0 + tx;
        float v = tile[tx][ty + i];
        __half h, l;
        split_h(v, h, l);
        g_xTh[(size_t)n * NROWS + k] = h;
        g_xTl[(size_t)n * NROWS + k] = l;
    }
}

__global__ void colsumT_kernel(){
    int c = blockIdx.x;
    const __half* ph = g_tTh + (size_t)c * NMEAS;
    const __half* pl = g_tTl + (size_t)c * NMEAS;
    float acc = 0.f;
    for (int k = threadIdx.x; k < NMEAS; k += 256){
        float v = __half2float(ph[k]) + __half2float(pl[k]);
        acc = fmaf(v, v, acc);
    }
    #pragma unroll
    for (int o = 16; o; o >>= 1) acc += __shfl_xor_sync(0xffffffffu, acc, o);
    __shared__ float smf[8];
    if ((threadIdx.x & 31) == 0) smf[threadIdx.x >> 5] = acc;
    __syncthreads();
    if (threadIdx.x < 8){
        float a = smf[threadIdx.x];
        #pragma unroll
        for (int o = 4; o; o >>= 1) a += __shfl_xor_sync(0xffu, a, o);
        if (threadIdx.x == 0) g_colacc[c] = a;
    }
}

__global__ void finalize_kernel(const float* __restrict__ gamma, int iter){
    int c = threadIdx.x;
    if (c >= NB) return;
    float taa = (float)g_taa;
    float tww = taa;
    float g = gamma[iter];
    float v2 = (g_colacc[c] - (float)MSEC * SIGMA2f) / taa;
    float tau2 = v2 / (float)NROWS * ((float)NROWS + (g*g - 2.0f*g) * (float)MSEC)
               + g * g * tww * SIGMA2f / (float)NROWS;
    g_coef[c] = SCALEf / tau2;
}

// ---------------- launch ----------------------------------------------------
extern "C" void kernel_launch(void* const* d_in, const int* in_sizes, int n_in,
                              void* d_out, int out_size)
{
    const float* x     = (const float*)d_in[0];
    const float* noise = (const float*)d_in[2];
    const float* A     = (const float*)d_in[3];
    const float* W     = (const float*)d_in[4];
    const float* gamma = (const float*)d_in[5];
    float* out = (float*)d_out;

    cudaFuncSetAttribute((const void*)gemm_t_split_kernel,
                         cudaFuncAttributeMaxDynamicSharedMemorySize, DYN_SMEM);
    cudaFuncSetAttribute((const void*)gemm_s_kernel,
                         cudaFuncAttributeMaxDynamicSharedMemorySize, DYN_SMEM);

    __half *dA16, *dW16;
    cudaGetSymbolAddress((void**)&dA16, g_A16);
    cudaGetSymbolAddress((void**)&dW16, g_W16);

    const long n4 = (long)NMEAS * NROWS / 4;

    init_scalars_kernel<<<1, 32>>>();
    conv_f16_kernel<<<2048, 256>>>(A, dA16, n4, 1);   // also computes taa
    conv_f16_kernel<<<2048, 256>>>(W, dW16, n4, 0);
    transpose_x_kernel<<<dim3(NROWS/32, NBP/32), dim3(32, 8)>>>(x);

    // y = A x + noise (t0 = y)
    gemm_t_split_kernel<<<dim3(NMEAS/BM, NBP/BN, KSPLIT), 256, DYN_SMEM>>>(1);
    reduce_t_kernel<<<dim3(NMEAS/256, NB), 256>>>(noise, 1);

    for (int it = 0; it < MAXITR; it++){
        colsumT_kernel<<<NB, 256>>>();
        finalize_kernel<<<1, 512>>>(gamma, it);
        gemm_s_kernel<<<dim3(NROWS/BM, NBP/BN), 256, DYN_SMEM>>>(gamma, it, out);
        if (it < MAXITR - 1){
            gemm_t_split_kernel<<<dim3(NMEAS/BM, NBP/BN, KSPLIT), 256, DYN_SMEM>>>(0);
            reduce_t_kernel<<<dim3(NMEAS/256, NB), 256>>>(noise, 0);
        }
    }
}

// round 7
// speedup vs baseline: 5.6831x; 1.1321x over previous
#include <cuda_runtime.h>
#include <cuda_fp16.h>
#include <cstdint>
#include <math.h>

// ---------------- Problem constants ----------------
#define NROWS 16384      // N
#define NMEAS 5120       // n
#define NB    500        // batch
#define NBP   512        // padded batch
#define MSEC  32
#define SIGMA2f 0.2f
#define SCALEf  3.1622776601683795f
#define MAXITR 4

// Tile config
#define BM 128
#define BN 128
#define BK 32
#define KSPLIT 8
#define KCHUNK (NROWS / KSPLIT)     // 2048
#define NTHREADS 512

#define STAGES 6
#define STAGE_BYTES 24576          // A 8K | Bh 8K | Bl 8K
#define OFF_BH 8192
#define OFF_BL 16384
#define DYN_SMEM (STAGES * STAGE_BYTES)

// ---------------- Scratch (device globals) ----------------
__device__ __half g_A16[(size_t)NMEAS * NROWS];     // A single fp16
__device__ __half g_W16[(size_t)NROWS * NMEAS];     // W single fp16
__device__ __half g_xTh[(size_t)NBP * NROWS];
__device__ __half g_xTl[(size_t)NBP * NROWS];
__device__ __half g_sTh[(size_t)NBP * NROWS];
__device__ __half g_sTl[(size_t)NBP * NROWS];
__device__ __half g_tTh[(size_t)NBP * NMEAS];
__device__ __half g_tTl[(size_t)NBP * NMEAS];
__device__ float  g_yT[(size_t)NBP * NMEAS];
__device__ float  g_part[(size_t)KSPLIT * NBP * NMEAS];   // [z][col][row]
__device__ double g_taa;
__device__ float  g_colacc[NBP];
__device__ float  g_coef[NBP];

// ---------------- PTX helpers ----------------
__device__ __forceinline__ uint32_t smem_u32(const void* p){
    uint32_t a;
    asm("{ .reg .u64 t; cvta.to.shared.u64 t, %1; cvt.u32.u64 %0, t; }"
        : "=r"(a) : "l"(p));
    return a;
}
__device__ __forceinline__ void cpasync16(uint32_t dst, const void* src){
    asm volatile("cp.async.cg.shared.global [%0], [%1], 16;"
                 :: "r"(dst), "l"(src) : "memory");
}
#define CP_COMMIT()  asm volatile("cp.async.commit_group;" ::: "memory")
#define CP_WAIT(n)   asm volatile("cp.async.wait_group %0;" :: "n"(n) : "memory")

__device__ __forceinline__ void ldsm4(uint32_t& r0, uint32_t& r1, uint32_t& r2,
                                      uint32_t& r3, uint32_t addr){
    asm volatile("ldmatrix.sync.aligned.m8n8.x4.shared.b16 {%0,%1,%2,%3}, [%4];"
                 : "=r"(r0), "=r"(r1), "=r"(r2), "=r"(r3) : "r"(addr));
}
__device__ __forceinline__ void mma16816(float* d, const uint32_t* a, const uint32_t* b){
    asm volatile(
        "mma.sync.aligned.m16n8k16.row.col.f32.f16.f16.f32 "
        "{%0,%1,%2,%3}, {%4,%5,%6,%7}, {%8,%9}, {%0,%1,%2,%3};"
        : "+f"(d[0]), "+f"(d[1]), "+f"(d[2]), "+f"(d[3])
        : "r"(a[0]), "r"(a[1]), "r"(a[2]), "r"(a[3]), "r"(b[0]), "r"(b[1]));
}
__device__ __forceinline__ uint32_t pack_h(__half a, __half b){
    return (uint32_t)__half_as_ushort(a) | ((uint32_t)__half_as_ushort(b) << 16);
}
__device__ __forceinline__ void split_h(float v, __half& hi, __half& lo){
    hi = __float2half_rn(v);
    lo = __float2half_rn(v - __half2float(hi));
}

// ---------------- fp16 2-term GEMM mainloop (512 threads, 16 warps) --------
// acc[2][4][4] += A_fp16[128 x K] * (Bh + Bl)[128 x K]^T ; warp tile 32x32
__device__ __forceinline__ void gemm_loop_f16(
    const __half* __restrict__ Am,
    const __half* __restrict__ Bh, const __half* __restrict__ Bl,
    int strideA, int strideB, int S, uint32_t smbase, float acc[2][4][4])
{
    const int tid = threadIdx.x, lane = tid & 31, wid = tid >> 5;
    const int wm = wid >> 2, wn = wid & 3;          // 4 x 4 warp grid

    // cp.async: thread -> row = tid>>2 (0..127), chunk col c = tid&3
    const int row = tid >> 2;
    const int c  = tid & 3;
    const int sw = (row >> 1) & 3;
    const uint32_t o0 = (uint32_t)(row * 64 + (c ^ sw) * 16);
    const int koff = c * 8;

    const __half* aP = Am + (size_t)row * strideA + koff;
    const __half* bH = Bh + (size_t)row * strideB + koff;
    const __half* bL = Bl + (size_t)row * strideB + koff;

    auto issue = [&](int s){
        uint32_t base = smbase + (uint32_t)(s % STAGES) * STAGE_BYTES;
        cpasync16(base + o0,          aP + s * BK);
        cpasync16(base + OFF_BH + o0, bH + s * BK);
        cpasync16(base + OFF_BL + o0, bL + s * BK);
    };

    // LDSM addressing: A warp rows = wm*32..+31, B warp cols = wn*32..+31
    const int rA = wm * 32 + (lane & 15);
    const int swA = (rA >> 1) & 3;
    const int cA = lane >> 4;
    const uint32_t ldA = smbase + rA * 64;
    const int rB = wn * 32 + (lane & 7) + ((lane >> 4) & 1) * 8;
    const int swB = (rB >> 1) & 3;
    const int cBc = (lane >> 3) & 1;
    const uint32_t ldB = smbase + rB * 64;

    #pragma unroll
    for (int p = 0; p < STAGES - 1; p++){
        issue(p);
        CP_COMMIT();
    }

    for (int s = 0; s < S; s++){
        CP_WAIT(STAGES - 2);
        __syncthreads();
        const uint32_t so = (uint32_t)(s % STAGES) * STAGE_BYTES;
        #pragma unroll
        for (int kk = 0; kk < 2; kk++){
            uint32_t ar[2][4], bh[4][2], bl[4][2];
            const uint32_t aoffk = (uint32_t)(((cA + 2 * kk) ^ swA) * 16);
            const uint32_t boffk = (uint32_t)(((cBc + 2 * kk) ^ swB) * 16);
            #pragma unroll
            for (int mf = 0; mf < 2; mf++){
                uint32_t ad = ldA + so + mf * 1024 + aoffk;
                ldsm4(ar[mf][0], ar[mf][1], ar[mf][2], ar[mf][3], ad);
            }
            #pragma unroll
            for (int np = 0; np < 2; np++){
                uint32_t bd = ldB + so + OFF_BH + np * 1024 + boffk;
                ldsm4(bh[np*2][0], bh[np*2][1], bh[np*2+1][0], bh[np*2+1][1], bd);
                ldsm4(bl[np*2][0], bl[np*2][1], bl[np*2+1][0], bl[np*2+1][1], bd + 8192);
            }
            #pragma unroll
            for (int mf = 0; mf < 2; mf++)
                #pragma unroll
                for (int nf = 0; nf < 4; nf++)
                    mma16816(acc[mf][nf], ar[mf], bh[nf]);
            #pragma unroll
            for (int mf = 0; mf < 2; mf++)
                #pragma unroll
                for (int nf = 0; nf < 4; nf++)
                    mma16816(acc[mf][nf], ar[mf], bl[nf]);
        }
        int nx = s + STAGES - 1;
        if (nx < S) issue(nx);
        CP_COMMIT();
    }
}

#define ZERO_ACC(acc)                                         \
    float acc[2][4][4];                                       \
    _Pragma("unroll")                                         \
    for (int i = 0; i < 2; i++)                               \
        _Pragma("unroll")                                     \
        for (int j = 0; j < 4; j++)                           \
            _Pragma("unroll")                                 \
            for (int k = 0; k < 4; k++) acc[i][j][k] = 0.f;

// ---------------- GEMM 1 (split-K): partials of A @ X -> g_part[z][c][r] ---
__global__ __launch_bounds__(NTHREADS, 1)
void gemm_t_split_kernel(int first)
{
    extern __shared__ char sm[];
    const int row0 = blockIdx.x * BM, col0 = blockIdx.y * BN, z = blockIdx.z;
    const __half* Bh = (first ? g_xTh : g_sTh) + (size_t)col0 * NROWS + (size_t)z * KCHUNK;
    const __half* Bl = (first ? g_xTl : g_sTl) + (size_t)col0 * NROWS + (size_t)z * KCHUNK;

    ZERO_ACC(acc);
    gemm_loop_f16(g_A16 + (size_t)row0 * NROWS + (size_t)z * KCHUNK,
                  Bh, Bl, NROWS, NROWS, KCHUNK / BK, smem_u32(sm), acc);

    const int lane = threadIdx.x & 31, wid = threadIdx.x >> 5;
    const int wm = wid >> 2, wn = wid & 3;
    const int r0 = row0 + wm * 32 + (lane >> 2);
    const int c0 = col0 + wn * 32 + (lane & 3) * 2;
    float* P = g_part + (size_t)z * NBP * NMEAS;
    #pragma unroll
    for (int mf = 0; mf < 2; mf++){
        #pragma unroll
        for (int nf = 0; nf < 4; nf++){
            int r = r0 + mf * 16, cc = c0 + nf * 8;
            P[(size_t)cc * NMEAS + r]           = acc[mf][nf][0];
            P[(size_t)(cc + 1) * NMEAS + r]     = acc[mf][nf][1];
            P[(size_t)cc * NMEAS + r + 8]       = acc[mf][nf][2];
            P[(size_t)(cc + 1) * NMEAS + r + 8] = acc[mf][nf][3];
        }
    }
}

// ---------------- reduce partials + t epilogue (writes tTh/tTl) ------------
__global__ void reduce_t_kernel(const float* __restrict__ noise, int first)
{
    const int c = blockIdx.y;
    const int row = blockIdx.x * 256 + threadIdx.x;
    float a = 0.f;
    #pragma unroll
    for (int z = 0; z < KSPLIT; z++)
        a += g_part[((size_t)z * NBP + c) * NMEAS + row];
    float v;
    if (first){
        v = noise[(size_t)row * NB + c] + a;
        g_yT[(size_t)c * NMEAS + row] = v;
    } else {
        v = g_yT[(size_t)c * NMEAS + row] - a;
    }
    __half h, l;
    split_h(v, h, l);
    g_tTh[(size_t)c * NMEAS + row] = h;
    g_tTl[(size_t)c * NMEAS + row] = l;
}

// ---------------- GEMM 2 + fused per-section softmax -----------------------
__global__ __launch_bounds__(NTHREADS, 1)
void gemm_s_kernel(const float* __restrict__ gammap, int iter, float* __restrict__ outp)
{
    extern __shared__ char sm[];
    const int row0 = blockIdx.x * BM, col0 = blockIdx.y * BN;

    ZERO_ACC(acc);
    gemm_loop_f16(g_W16 + (size_t)row0 * NMEAS,
                  g_tTh + (size_t)col0 * NMEAS, g_tTl + (size_t)col0 * NMEAS,
                  NMEAS, NMEAS, NMEAS / BK, smem_u32(sm), acc);

    const int lane = threadIdx.x & 31, wid = threadIdx.x >> 5;
    const int wm = wid >> 2, wn = wid & 3;
    const float g = gammap[iter];
    const int rr = row0 + wm * 32 + (lane >> 2);    // warp covers one 32-row section
    const int ccb = col0 + wn * 32 + (lane & 3) * 2;

    #pragma unroll
    for (int nf = 0; nf < 4; nf++){
        #pragma unroll
        for (int j = 0; j < 2; j++){
            int col = ccb + nf * 8 + j;
            bool valid = col < NB;
            float cf = valid ? g_coef[col] : 0.f;
            float z0 = acc[0][nf][j    ] * g;
            float z1 = acc[0][nf][j + 2] * g;
            float z2 = acc[1][nf][j    ] * g;
            float z3 = acc[1][nf][j + 2] * g;
            if (iter > 0 && valid){
                const __half* sh = g_sTh + (size_t)col * NROWS;
                const __half* sl = g_sTl + (size_t)col * NROWS;
                z0 += __half2float(sh[rr])      + __half2float(sl[rr]);
                z1 += __half2float(sh[rr + 8])  + __half2float(sl[rr + 8]);
                z2 += __half2float(sh[rr + 16]) + __half2float(sl[rr + 16]);
                z3 += __half2float(sh[rr + 24]) + __half2float(sl[rr + 24]);
            }
            z0 *= cf; z1 *= cf; z2 *= cf; z3 *= cf;
            float m = fmaxf(fmaxf(z0, z1), fmaxf(z2, z3));
            #pragma unroll
            for (int o = 4; o <= 16; o <<= 1)
                m = fmaxf(m, __shfl_xor_sync(0xffffffffu, m, o));
            float e0 = __expf(z0 - m), e1 = __expf(z1 - m);
            float e2 = __expf(z2 - m), e3 = __expf(z3 - m);
            float su = (e0 + e1) + (e2 + e3);
            #pragma unroll
            for (int o = 4; o <= 16; o <<= 1)
                su += __shfl_xor_sync(0xffffffffu, su, o);
            float inv = __fdividef(1.f, su);
            if (valid){
                float v0 = e0 * inv, v1 = e1 * inv, v2 = e2 * inv, v3 = e3 * inv;
                if (iter == MAXITR - 1){
                    outp[(size_t)rr * NB + col]        = v0;
                    outp[(size_t)(rr + 8)  * NB + col] = v1;
                    outp[(size_t)(rr + 16) * NB + col] = v2;
                    outp[(size_t)(rr + 24) * NB + col] = v3;
                } else {
                    __half* sh = g_sTh + (size_t)col * NROWS;
                    __half* sl = g_sTl + (size_t)col * NROWS;
                    __half h, l;
                    split_h(v0, h, l); sh[rr]      = h; sl[rr]      = l;
                    split_h(v1, h, l); sh[rr + 8]  = h; sl[rr + 8]  = l;
                    split_h(v2, h, l); sh[rr + 16] = h; sl[rr + 16] = l;
                    split_h(v3, h, l); sh[rr + 24] = h; sl[rr + 24] = l;
                }
            }
        }
    }
}

// ---------------- conversion / small kernels --------------------------------
__global__ void init_scalars_kernel(){
    if (threadIdx.x == 0) g_taa = 0.0;
}

__global__ void conv_f16_kernel(const float* __restrict__ src,
                                __half* __restrict__ dst, long n4, int do_taa)
{
    double t = 0.0;
    const float4* s4 = (const float4*)src;
    uint2* d2 = (uint2*)dst;
    for (long i = (long)blockIdx.x * blockDim.x + threadIdx.x; i < n4;
         i += (long)gridDim.x * blockDim.x){
        float4 v = s4[i];
        d2[i] = make_uint2(pack_h(__float2half_rn(v.x), __float2half_rn(v.y)),
                           pack_h(__float2half_rn(v.z), __float2half_rn(v.w)));
        if (do_taa)
            t += (double)v.x*v.x + (double)v.y*v.y + (double)v.z*v.z + (double)v.w*v.w;
    }
    if (do_taa){
        __shared__ double smd[256];
        smd[threadIdx.x] = t;
        __syncthreads();
        for (int s = 128; s > 0; s >>= 1){
            if (threadIdx.x < s) smd[threadIdx.x] += smd[threadIdx.x + s];
            __syncthreads();
        }
        if (threadIdx.x == 0) atomicAdd(&g_taa, smd[0]);
    }
}

__global__ void transpose_x_kernel(const float* __restrict__ x){
    __shared__ float tile[32][33];
    int k0 = blockIdx.x * 32, n0 = blockIdx.y * 32;
    int tx = threadIdx.x, ty = threadIdx.y;
    #pragma unroll
    for (int i = 0; i < 32; i += 8){
        int k = k0 + ty + i, n = n0 + tx;
        tile[ty + i][tx] = (n < NB) ? x[(size_t)k * NB + n] : 0.f;
    }
    __syncthreads();
    #pragma unroll
    for (int i = 0; i < 32; i += 8){
        int n = n0 + ty + i, k = k0 + tx;
        float v = tile[tx][ty + i];
        __half h, l;
        split_h(v, h, l);
        g_xTh[(size_t)n * NROWS + k] = h;
        g_xTl[(size_t)n * NROWS + k] = l;
    }
}

__global__ void colsumT_kernel(){
    int c = blockIdx.x;
    const __half* ph = g_tTh + (size_t)c * NMEAS;
    const __half* pl = g_tTl + (size_t)c * NMEAS;
    float acc = 0.f;
    for (int k = threadIdx.x; k < NMEAS; k += 256){
        float v = __half2float(ph[k]) + __half2float(pl[k]);
        acc = fmaf(v, v, acc);
    }
    #pragma unroll
    for (int o = 16; o; o >>= 1) acc += __shfl_xor_sync(0xffffffffu, acc, o);
    __shared__ float smf[8];
    if ((threadIdx.x & 31) == 0) smf[threadIdx.x >> 5] = acc;
    __syncthreads();
    if (threadIdx.x < 8){
        float a = smf[threadIdx.x];
        #pragma unroll
        for (int o = 4; o; o >>= 1) a += __shfl_xor_sync(0xffu, a, o);
        if (threadIdx.x == 0) g_colacc[c] = a;
    }
}

__global__ void finalize_kernel(const float* __restrict__ gamma, int iter){
    int c = threadIdx.x;
    if (c >= NB) return;
    float taa = (float)g_taa;
    float tww = taa;
    float g = gamma[iter];
    float v2 = (g_colacc[c] - (float)MSEC * SIGMA2f) / taa;
    float tau2 = v2 / (float)NROWS * ((float)NROWS + (g*g - 2.0f*g) * (float)MSEC)
               + g * g * tww * SIGMA2f / (float)NROWS;
    g_coef[c] = SCALEf / tau2;
}

// ---------------- launch ----------------------------------------------------
extern "C" void kernel_launch(void* const* d_in, const int* in_sizes, int n_in,
                              void* d_out, int out_size)
{
    const float* x     = (const float*)d_in[0];
    const float* noise = (const float*)d_in[2];
    const float* A     = (const float*)d_in[3];
    const float* W     = (const float*)d_in[4];
    const float* gamma = (const float*)d_in[5];
    float* out = (float*)d_out;

    cudaFuncSetAttribute((const void*)gemm_t_split_kernel,
                         cudaFuncAttributeMaxDynamicSharedMemorySize, DYN_SMEM);
    cudaFuncSetAttribute((const void*)gemm_s_kernel,
                         cudaFuncAttributeMaxDynamicSharedMemorySize, DYN_SMEM);

    __half *dA16, *dW16;
    cudaGetSymbolAddress((void**)&dA16, g_A16);
    cudaGetSymbolAddress((void**)&dW16, g_W16);

    const long n4 = (long)NMEAS * NROWS / 4;

    init_scalars_kernel<<<1, 32>>>();
    conv_f16_kernel<<<2048, 256>>>(A, dA16, n4, 1);   // also computes taa
    conv_f16_kernel<<<2048, 256>>>(W, dW16, n4, 0);
    transpose_x_kernel<<<dim3(NROWS/32, NBP/32), dim3(32, 8)>>>(x);

    // y = A x + noise (t0 = y)
    gemm_t_split_kernel<<<dim3(NMEAS/BM, NBP/BN, KSPLIT), NTHREADS, DYN_SMEM>>>(1);
    reduce_t_kernel<<<dim3(NMEAS/256, NB), 256>>>(noise, 1);

    for (int it = 0; it < MAXITR; it++){
        colsumT_kernel<<<NB, 256>>>();
        finalize_kernel<<<1, 512>>>(gamma, it);
        gemm_s_kernel<<<dim3(NROWS/BM, NBP/BN), NTHREADS, DYN_SMEM>>>(gamma, it, out);
        if (it < MAXITR - 1){
            gemm_t_split_kernel<<<dim3(NMEAS/BM, NBP/BN, KSPLIT), NTHREADS, DYN_SMEM>>>(0);
            reduce_t_kernel<<<dim3(NMEAS/256, NB), 256>>>(noise, 0);
        }
    }
}

// round 8
// speedup vs baseline: 5.8716x; 1.0332x over previous
#include <cuda_runtime.h>
#include <cuda_fp16.h>
#include <cstdint>
#include <math.h>

// ---------------- Problem constants ----------------
#define NROWS 16384      // N
#define NMEAS 5120       // n
#define NB    500        // batch
#define NBP   512        // padded batch
#define MSEC  32
#define SIGMA2f 0.2f
#define SCALEf  3.1622776601683795f
#define MAXITR 4

// Tile config
#define BM 128
#define BN 128
#define BK 64
#define KSPLIT 8
#define KCHUNK (NROWS / KSPLIT)     // 2048
#define NTHREADS 512

#define STAGES 4
#define STAGE_BYTES 49152          // A 16K | Bh 16K | Bl 16K (128B rows)
#define OFF_BH 16384
#define OFF_BL 32768
#define DYN_SMEM (STAGES * STAGE_BYTES)   // 192 KB

// ---------------- Scratch (device globals) ----------------
__device__ __half g_A16[(size_t)NMEAS * NROWS];     // A single fp16
__device__ __half g_W16[(size_t)NROWS * NMEAS];     // W single fp16
__device__ __half g_xTh[(size_t)NBP * NROWS];
__device__ __half g_xTl[(size_t)NBP * NROWS];
__device__ __half g_sTh[(size_t)NBP * NROWS];
__device__ __half g_sTl[(size_t)NBP * NROWS];
__device__ __half g_tTh[(size_t)NBP * NMEAS];
__device__ __half g_tTl[(size_t)NBP * NMEAS];
__device__ float  g_yT[(size_t)NBP * NMEAS];
__device__ float  g_part[(size_t)KSPLIT * NBP * NMEAS];   // [z][col][row]
__device__ double g_taa;
__device__ float  g_colacc[NBP];
__device__ float  g_coef[NBP];

// ---------------- PTX helpers ----------------
__device__ __forceinline__ uint32_t smem_u32(const void* p){
    uint32_t a;
    asm("{ .reg .u64 t; cvta.to.shared.u64 t, %1; cvt.u32.u64 %0, t; }"
        : "=r"(a) : "l"(p));
    return a;
}
__device__ __forceinline__ void cpasync16(uint32_t dst, const void* src){
    asm volatile("cp.async.cg.shared.global [%0], [%1], 16;"
                 :: "r"(dst), "l"(src) : "memory");
}
#define CP_COMMIT()  asm volatile("cp.async.commit_group;" ::: "memory")
#define CP_WAIT(n)   asm volatile("cp.async.wait_group %0;" :: "n"(n) : "memory")

__device__ __forceinline__ void ldsm4(uint32_t& r0, uint32_t& r1, uint32_t& r2,
                                      uint32_t& r3, uint32_t addr){
    asm volatile("ldmatrix.sync.aligned.m8n8.x4.shared.b16 {%0,%1,%2,%3}, [%4];"
                 : "=r"(r0), "=r"(r1), "=r"(r2), "=r"(r3) : "r"(addr));
}
__device__ __forceinline__ void mma16816(float* d, const uint32_t* a, const uint32_t* b){
    asm volatile(
        "mma.sync.aligned.m16n8k16.row.col.f32.f16.f16.f32 "
        "{%0,%1,%2,%3}, {%4,%5,%6,%7}, {%8,%9}, {%0,%1,%2,%3};"
        : "+f"(d[0]), "+f"(d[1]), "+f"(d[2]), "+f"(d[3])
        : "r"(a[0]), "r"(a[1]), "r"(a[2]), "r"(a[3]), "r"(b[0]), "r"(b[1]));
}
__device__ __forceinline__ uint32_t pack_h(__half a, __half b){
    return (uint32_t)__half_as_ushort(a) | ((uint32_t)__half_as_ushort(b) << 16);
}
__device__ __forceinline__ void split_h(float v, __half& hi, __half& lo){
    hi = __float2half_rn(v);
    lo = __float2half_rn(v - __half2float(hi));
}

// ---------------- fp16 2-term GEMM mainloop (BK=64, 512 threads) -----------
// acc[2][4][4] += A_fp16[128 x K] * (Bh + Bl)[128 x K]^T ; warp tile 32x32
// smem tiles: 128 rows x 64 halves (128 B rows), swizzle chunk ^= (row & 7)
struct Frags { uint32_t ar[2][4], bh[4][2], bl[4][2]; };

__device__ __forceinline__ void gemm_loop_f16(
    const __half* __restrict__ Am,
    const __half* __restrict__ Bh, const __half* __restrict__ Bl,
    int strideA, int strideB, int S, uint32_t smbase, float acc[2][4][4])
{
    const int tid = threadIdx.x, lane = tid & 31, wid = tid >> 5;
    const int wm = wid >> 2, wn = wid & 3;          // 4 x 4 warp grid

    // cp.async: thread -> row = tid>>2 (0..127), chunk pair c2 = (tid&3)*2
    const int row = tid >> 2;
    const int c2  = (tid & 3) * 2;
    const int sw  = row & 7;
    const uint32_t o0 = (uint32_t)(row * 128 + ((c2    ) ^ sw) * 16);
    const uint32_t o1 = (uint32_t)(row * 128 + ((c2 + 1) ^ sw) * 16);
    const int koff = c2 * 8;                        // halves

    const __half* aP = Am + (size_t)row * strideA + koff;
    const __half* bH = Bh + (size_t)row * strideB + koff;
    const __half* bL = Bl + (size_t)row * strideB + koff;

    auto issue = [&](int s){
        uint32_t base = smbase + (uint32_t)(s & (STAGES - 1)) * STAGE_BYTES;
        const __half* pa = aP + s * BK;
        const __half* pb = bH + s * BK;
        const __half* pq = bL + s * BK;
        cpasync16(base + o0,          pa);  cpasync16(base + o1,          pa + 8);
        cpasync16(base + OFF_BH + o0, pb);  cpasync16(base + OFF_BH + o1, pb + 8);
        cpasync16(base + OFF_BL + o0, pq);  cpasync16(base + OFF_BL + o1, pq + 8);
    };

    // LDSM addressing
    const int rA = wm * 32 + (lane & 15);
    const int swA = rA & 7;
    const int cA = lane >> 4;                       // 0/1
    const uint32_t ldA = smbase + rA * 128;
    const int rB = wn * 32 + (lane & 7) + ((lane >> 4) & 1) * 8;
    const int swB = rB & 7;
    const int cBc = (lane >> 3) & 1;
    const uint32_t ldB = smbase + rB * 128;

    auto load_frags = [&](Frags& f, uint32_t so, int kk){
        const uint32_t aoffk = (uint32_t)(((cA + 2 * kk) ^ swA) * 16);
        const uint32_t boffk = (uint32_t)(((cBc + 2 * kk) ^ swB) * 16);
        #pragma unroll
        for (int mf = 0; mf < 2; mf++){
            uint32_t ad = ldA + so + mf * 2048 + aoffk;   // 16 rows * 128 B
            ldsm4(f.ar[mf][0], f.ar[mf][1], f.ar[mf][2], f.ar[mf][3], ad);
        }
        #pragma unroll
        for (int np = 0; np < 2; np++){
            uint32_t bd = ldB + so + OFF_BH + np * 2048 + boffk;
            ldsm4(f.bh[np*2][0], f.bh[np*2][1], f.bh[np*2+1][0], f.bh[np*2+1][1], bd);
            ldsm4(f.bl[np*2][0], f.bl[np*2][1], f.bl[np*2+1][0], f.bl[np*2+1][1], bd + 16384);
        }
    };
    auto do_mmas = [&](Frags& f){
        #pragma unroll
        for (int mf = 0; mf < 2; mf++)
            #pragma unroll
            for (int nf = 0; nf < 4; nf++)
                mma16816(acc[mf][nf], f.ar[mf], f.bh[nf]);
        #pragma unroll
        for (int mf = 0; mf < 2; mf++)
            #pragma unroll
            for (int nf = 0; nf < 4; nf++)
                mma16816(acc[mf][nf], f.ar[mf], f.bl[nf]);
    };

    #pragma unroll
    for (int p = 0; p < STAGES - 1; p++){
        issue(p);
        CP_COMMIT();
    }

    Frags fr[2];
    for (int s = 0; s < S; s++){
        CP_WAIT(STAGES - 2);
        __syncthreads();
        const uint32_t so = (uint32_t)(s & (STAGES - 1)) * STAGE_BYTES;
        load_frags(fr[0], so, 0);
        #pragma unroll
        for (int kk = 0; kk < 4; kk++){
            if (kk < 3) load_frags(fr[(kk + 1) & 1], so, kk + 1);
            do_mmas(fr[kk & 1]);
        }
        int nx = s + STAGES - 1;
        if (nx < S) issue(nx);
        CP_COMMIT();
    }
}

#define ZERO_ACC(acc)                                         \
    float acc[2][4][4];                                       \
    _Pragma("unroll")                                         \
    for (int i = 0; i < 2; i++)                               \
        _Pragma("unroll")                                     \
        for (int j = 0; j < 4; j++)                           \
            _Pragma("unroll")                                 \
            for (int k = 0; k < 4; k++) acc[i][j][k] = 0.f;

// ---------------- GEMM 1 (split-K): partials of A @ X -> g_part[z][c][r] ---
__global__ __launch_bounds__(NTHREADS, 1)
void gemm_t_split_kernel(int first)
{
    extern __shared__ char sm[];
    const int row0 = blockIdx.x * BM, col0 = blockIdx.y * BN, z = blockIdx.z;
    const __half* Bh = (first ? g_xTh : g_sTh) + (size_t)col0 * NROWS + (size_t)z * KCHUNK;
    const __half* Bl = (first ? g_xTl : g_sTl) + (size_t)col0 * NROWS + (size_t)z * KCHUNK;

    ZERO_ACC(acc);
    gemm_loop_f16(g_A16 + (size_t)row0 * NROWS + (size_t)z * KCHUNK,
                  Bh, Bl, NROWS, NROWS, KCHUNK / BK, smem_u32(sm), acc);

    const int lane = threadIdx.x & 31, wid = threadIdx.x >> 5;
    const int wm = wid >> 2, wn = wid & 3;
    const int r0 = row0 + wm * 32 + (lane >> 2);
    const int c0 = col0 + wn * 32 + (lane & 3) * 2;
    float* P = g_part + (size_t)z * NBP * NMEAS;
    #pragma unroll
    for (int mf = 0; mf < 2; mf++){
        #pragma unroll
        for (int nf = 0; nf < 4; nf++){
            int r = r0 + mf * 16, cc = c0 + nf * 8;
            P[(size_t)cc * NMEAS + r]           = acc[mf][nf][0];
            P[(size_t)(cc + 1) * NMEAS + r]     = acc[mf][nf][1];
            P[(size_t)cc * NMEAS + r + 8]       = acc[mf][nf][2];
            P[(size_t)(cc + 1) * NMEAS + r + 8] = acc[mf][nf][3];
        }
    }
}

// ------- reduce partials + t epilogue + fused column sum-of-squares --------
__global__ void reduce_t_kernel(const float* __restrict__ noise, int first)
{
    const int c = blockIdx.y;
    const int row = blockIdx.x * 256 + threadIdx.x;
    float a = 0.f;
    #pragma unroll
    for (int z = 0; z < KSPLIT; z++)
        a += g_part[((size_t)z * NBP + c) * NMEAS + row];
    float v;
    if (first){
        v = noise[(size_t)row * NB + c] + a;
        g_yT[(size_t)c * NMEAS + row] = v;
    } else {
        v = g_yT[(size_t)c * NMEAS + row] - a;
    }
    __half h, l;
    split_h(v, h, l);
    g_tTh[(size_t)c * NMEAS + row] = h;
    g_tTl[(size_t)c * NMEAS + row] = l;

    // fused colsum of t^2
    float sq = v * v;
    #pragma unroll
    for (int o = 16; o; o >>= 1) sq += __shfl_xor_sync(0xffffffffu, sq, o);
    __shared__ float red[8];
    if ((threadIdx.x & 31) == 0) red[threadIdx.x >> 5] = sq;
    __syncthreads();
    if (threadIdx.x < 8){
        float t = red[threadIdx.x];
        #pragma unroll
        for (int o = 4; o; o >>= 1) t += __shfl_xor_sync(0xffu, t, o);
        if (threadIdx.x == 0) atomicAdd(&g_colacc[c], t);
    }
}

// ---------------- GEMM 2 + fused per-section softmax -----------------------
__global__ __launch_bounds__(NTHREADS, 1)
void gemm_s_kernel(const float* __restrict__ gammap, int iter, float* __restrict__ outp)
{
    extern __shared__ char sm[];
    const int row0 = blockIdx.x * BM, col0 = blockIdx.y * BN;

    ZERO_ACC(acc);
    gemm_loop_f16(g_W16 + (size_t)row0 * NMEAS,
                  g_tTh + (size_t)col0 * NMEAS, g_tTl + (size_t)col0 * NMEAS,
                  NMEAS, NMEAS, NMEAS / BK, smem_u32(sm), acc);

    const int lane = threadIdx.x & 31, wid = threadIdx.x >> 5;
    const int wm = wid >> 2, wn = wid & 3;
    const float g = gammap[iter];
    const int rr = row0 + wm * 32 + (lane >> 2);    // warp covers one 32-row section
    const int ccb = col0 + wn * 32 + (lane & 3) * 2;

    #pragma unroll
    for (int nf = 0; nf < 4; nf++){
        #pragma unroll
        for (int j = 0; j < 2; j++){
            int col = ccb + nf * 8 + j;
            bool valid = col < NB;
            float cf = valid ? g_coef[col] : 0.f;
            float z0 = acc[0][nf][j    ] * g;
            float z1 = acc[0][nf][j + 2] * g;
            float z2 = acc[1][nf][j    ] * g;
            float z3 = acc[1][nf][j + 2] * g;
            if (iter > 0 && valid){
                const __half* sh = g_sTh + (size_t)col * NROWS;
                const __half* sl = g_sTl + (size_t)col * NROWS;
                z0 += __half2float(sh[rr])      + __half2float(sl[rr]);
                z1 += __half2float(sh[rr + 8])  + __half2float(sl[rr + 8]);
                z2 += __half2float(sh[rr + 16]) + __half2float(sl[rr + 16]);
                z3 += __half2float(sh[rr + 24]) + __half2float(sl[rr + 24]);
            }
            z0 *= cf; z1 *= cf; z2 *= cf; z3 *= cf;
            float m = fmaxf(fmaxf(z0, z1), fmaxf(z2, z3));
            #pragma unroll
            for (int o = 4; o <= 16; o <<= 1)
                m = fmaxf(m, __shfl_xor_sync(0xffffffffu, m, o));
            float e0 = __expf(z0 - m), e1 = __expf(z1 - m);
            float e2 = __expf(z2 - m), e3 = __expf(z3 - m);
            float su = (e0 + e1) + (e2 + e3);
            #pragma unroll
            for (int o = 4; o <= 16; o <<= 1)
                su += __shfl_xor_sync(0xffffffffu, su, o);
            float inv = __fdividef(1.f, su);
            if (valid){
                float v0 = e0 * inv, v1 = e1 * inv, v2 = e2 * inv, v3 = e3 * inv;
                if (iter == MAXITR - 1){
                    outp[(size_t)rr * NB + col]        = v0;
                    outp[(size_t)(rr + 8)  * NB + col] = v1;
                    outp[(size_t)(rr + 16) * NB + col] = v2;
                    outp[(size_t)(rr + 24) * NB + col] = v3;
                } else {
                    __half* sh = g_sTh + (size_t)col * NROWS;
                    __half* sl = g_sTl + (size_t)col * NROWS;
                    __half h, l;
                    split_h(v0, h, l); sh[rr]      = h; sl[rr]      = l;
                    split_h(v1, h, l); sh[rr + 8]  = h; sl[rr + 8]  = l;
                    split_h(v2, h, l); sh[rr + 16] = h; sl[rr + 16] = l;
                    split_h(v3, h, l); sh[rr + 24] = h; sl[rr + 24] = l;
                }
            }
        }
    }
}

// ---------------- conversion / small kernels --------------------------------
__global__ void init_scalars_kernel(){
    if (threadIdx.x == 0) g_taa = 0.0;
    if (threadIdx.x < NBP) g_colacc[threadIdx.x] = 0.f;
}

__global__ void conv_f16_kernel(const float* __restrict__ src,
                                __half* __restrict__ dst, long n4, int do_taa)
{
    double t = 0.0;
    const float4* s4 = (const float4*)src;
    uint2* d2 = (uint2*)dst;
    for (long i = (long)blockIdx.x * blockDim.x + threadIdx.x; i < n4;
         i += (long)gridDim.x * blockDim.x){
        float4 v = s4[i];
        d2[i] = make_uint2(pack_h(__float2half_rn(v.x), __float2half_rn(v.y)),
                           pack_h(__float2half_rn(v.z), __float2half_rn(v.w)));
        if (do_taa)
            t += (double)v.x*v.x + (double)v.y*v.y + (double)v.z*v.z + (double)v.w*v.w;
    }
    if (do_taa){
        __shared__ double smd[256];
        smd[threadIdx.x] = t;
        __syncthreads();
        for (int s = 128; s > 0; s >>= 1){
            if (threadIdx.x < s) smd[threadIdx.x] += smd[threadIdx.x + s];
            __syncthreads();
        }
        if (threadIdx.x == 0) atomicAdd(&g_taa, smd[0]);
    }
}

__global__ void transpose_x_kernel(const float* __restrict__ x){
    __shared__ float tile[32][33];
    int k0 = blockIdx.x * 32, n0 = blockIdx.y * 32;
    int tx = threadIdx.x, ty = threadIdx.y;
    #pragma unroll
    for (int i = 0; i < 32; i += 8){
        int k = k0 + ty + i, n = n0 + tx;
        tile[ty + i][tx] = (n < NB) ? x[(size_t)k * NB + n] : 0.f;
    }
    __syncthreads();
    #pragma unroll
    for (int i = 0; i < 32; i += 8){
        int n = n0 + ty + i, k = k0 + tx;
        float v = tile[tx][ty + i];
        __half h, l;
        split_h(v, h, l);
        g_xTh[(size_t)n * NROWS + k] = h;
        g_xTl[(size_t)n * NROWS + k] = l;
    }
}

// consume colacc -> coef, then zero colacc for next iteration's accumulation
__global__ void finalize_kernel(const float* __restrict__ gamma, int iter){
    int c = threadIdx.x;
    if (c < NB){
        float taa = (float)g_taa;
        float tww = taa;
        float g = gamma[iter];
        float v2 = (g_colacc[c] - (float)MSEC * SIGMA2f) / taa;
        float tau2 = v2 / (float)NROWS * ((float)NROWS + (g*g - 2.0f*g) * (float)MSEC)
                   + g * g * tww * SIGMA2f / (float)NROWS;
        g_coef[c] = SCALEf / tau2;
    }
    if (c < NBP) g_colacc[c] = 0.f;
}

// ---------------- launch ----------------------------------------------------
extern "C" void kernel_launch(void* const* d_in, const int* in_sizes, int n_in,
                              void* d_out, int out_size)
{
    const float* x     = (const float*)d_in[0];
    const float* noise = (const float*)d_in[2];
    const float* A     = (const float*)d_in[3];
    const float* W     = (const float*)d_in[4];
    const float* gamma = (const float*)d_in[5];
    float* out = (float*)d_out;

    cudaFuncSetAttribute((const void*)gemm_t_split_kernel,
                         cudaFuncAttributeMaxDynamicSharedMemorySize, DYN_SMEM);
    cudaFuncSetAttribute((const void*)gemm_s_kernel,
                         cudaFuncAttributeMaxDynamicSharedMemorySize, DYN_SMEM);

    __half *dA16, *dW16;
    cudaGetSymbolAddress((void**)&dA16, g_A16);
    cudaGetSymbolAddress((void**)&dW16, g_W16);

    const long n4 = (long)NMEAS * NROWS / 4;

    init_scalars_kernel<<<1, 512>>>();
    conv_f16_kernel<<<2048, 256>>>(A, dA16, n4, 1);   // also computes taa
    conv_f16_kernel<<<2048, 256>>>(W, dW16, n4, 0);
    transpose_x_kernel<<<dim3(NROWS/32, NBP/32), dim3(32, 8)>>>(x);

    // y = A x + noise (t0 = y); reduce_t also accumulates colacc(t0)
    gemm_t_split_kernel<<<dim3(NMEAS/BM, NBP/BN, KSPLIT), NTHREADS, DYN_SMEM>>>(1);
    reduce_t_kernel<<<dim3(NMEAS/256, NB), 256>>>(noise, 1);

    for (int it = 0; it < MAXITR; it++){
        finalize_kernel<<<1, 512>>>(gamma, it);
        gemm_s_kernel<<<dim3(NROWS/BM, NBP/BN), NTHREADS, DYN_SMEM>>>(gamma, it, out);
        if (it < MAXITR - 1){
            gemm_t_split_kernel<<<dim3(NMEAS/BM, NBP/BN, KSPLIT), NTHREADS, DYN_SMEM>>>(0);
            reduce_t_kernel<<<dim3(NMEAS/256, NB), 256>>>(noise, 0);
        }
    }
}

// round 9
// speedup vs baseline: 6.0812x; 1.0357x over previous
#include <cuda_runtime.h>
#include <cuda_fp16.h>
#include <cstdint>
#include <math.h>

// ---------------- Problem constants ----------------
#define NROWS 16384      // N
#define NMEAS 5120       // n
#define NB    500        // batch
#define NBP   512        // padded batch
#define MSEC  32
#define SIGMA2f 0.2f
#define SCALEf  3.1622776601683795f
#define MAXITR 4

// Tile config
#define BM 128
#define BN 128
#define BK 64
#define KSPLIT 8
#define KCHUNK (NROWS / KSPLIT)     // 2048
#define KSPLIT_S 2
#define KCHUNK_S (NMEAS / KSPLIT_S) // 2560
#define NTHREADS 512

#define STAGES 4
#define STAGE_BYTES 49152          // A 16K | Bh 16K | Bl 16K (128B rows)
#define OFF_BH 16384
#define OFF_BL 32768
#define DYN_SMEM (STAGES * STAGE_BYTES)   // 192 KB

// ---------------- Scratch (device globals) ----------------
__device__ __half g_A16[(size_t)NMEAS * NROWS];     // A single fp16
__device__ __half g_W16[(size_t)NROWS * NMEAS];     // W single fp16
__device__ __half g_xTh[(size_t)NBP * NROWS];
__device__ __half g_xTl[(size_t)NBP * NROWS];
__device__ __half g_sTh[(size_t)NBP * NROWS];
__device__ __half g_sTl[(size_t)NBP * NROWS];
__device__ __half g_tTh[(size_t)NBP * NMEAS];
__device__ __half g_tTl[(size_t)NBP * NMEAS];
__device__ float  g_yT[(size_t)NBP * NMEAS];
// shared partial buffer: gemm_t uses [8][NBP][NMEAS]; gemm_s uses [2][NBP][NROWS]
__device__ float  g_part[(size_t)KSPLIT * NBP * NMEAS];
__device__ double g_taa;
__device__ float  g_colacc[NBP];
__device__ float  g_coef[NBP];

// ---------------- PTX helpers ----------------
__device__ __forceinline__ uint32_t smem_u32(const void* p){
    uint32_t a;
    asm("{ .reg .u64 t; cvta.to.shared.u64 t, %1; cvt.u32.u64 %0, t; }"
        : "=r"(a) : "l"(p));
    return a;
}
__device__ __forceinline__ void cpasync16(uint32_t dst, const void* src){
    asm volatile("cp.async.cg.shared.global [%0], [%1], 16;"
                 :: "r"(dst), "l"(src) : "memory");
}
#define CP_COMMIT()  asm volatile("cp.async.commit_group;" ::: "memory")
#define CP_WAIT(n)   asm volatile("cp.async.wait_group %0;" :: "n"(n) : "memory")

__device__ __forceinline__ void ldsm4(uint32_t& r0, uint32_t& r1, uint32_t& r2,
                                      uint32_t& r3, uint32_t addr){
    asm volatile("ldmatrix.sync.aligned.m8n8.x4.shared.b16 {%0,%1,%2,%3}, [%4];"
                 : "=r"(r0), "=r"(r1), "=r"(r2), "=r"(r3) : "r"(addr));
}
__device__ __forceinline__ void mma16816(float* d, const uint32_t* a, const uint32_t* b){
    asm volatile(
        "mma.sync.aligned.m16n8k16.row.col.f32.f16.f16.f32 "
        "{%0,%1,%2,%3}, {%4,%5,%6,%7}, {%8,%9}, {%0,%1,%2,%3};"
        : "+f"(d[0]), "+f"(d[1]), "+f"(d[2]), "+f"(d[3])
        : "r"(a[0]), "r"(a[1]), "r"(a[2]), "r"(a[3]), "r"(b[0]), "r"(b[1]));
}
__device__ __forceinline__ uint32_t pack_h(__half a, __half b){
    return (uint32_t)__half_as_ushort(a) | ((uint32_t)__half_as_ushort(b) << 16);
}
__device__ __forceinline__ void split_h(float v, __half& hi, __half& lo){
    hi = __float2half_rn(v);
    lo = __float2half_rn(v - __half2float(hi));
}

// ---------------- fp16 2-term GEMM mainloop (BK=64, 512 threads) -----------
struct Frags { uint32_t ar[2][4], bh[4][2], bl[4][2]; };

__device__ __forceinline__ void gemm_loop_f16(
    const __half* __restrict__ Am,
    const __half* __restrict__ Bh, const __half* __restrict__ Bl,
    int strideA, int strideB, int S, uint32_t smbase, float acc[2][4][4])
{
    const int tid = threadIdx.x, lane = tid & 31, wid = tid >> 5;
    const int wm = wid >> 2, wn = wid & 3;          // 4 x 4 warp grid

    const int row = tid >> 2;
    const int c2  = (tid & 3) * 2;
    const int sw  = row & 7;
    const uint32_t o0 = (uint32_t)(row * 128 + ((c2    ) ^ sw) * 16);
    const uint32_t o1 = (uint32_t)(row * 128 + ((c2 + 1) ^ sw) * 16);
    const int koff = c2 * 8;

    const __half* aP = Am + (size_t)row * strideA + koff;
    const __half* bH = Bh + (size_t)row * strideB + koff;
    const __half* bL = Bl + (size_t)row * strideB + koff;

    auto issue = [&](int s){
        uint32_t base = smbase + (uint32_t)(s & (STAGES - 1)) * STAGE_BYTES;
        const __half* pa = aP + s * BK;
        const __half* pb = bH + s * BK;
        const __half* pq = bL + s * BK;
        cpasync16(base + o0,          pa);  cpasync16(base + o1,          pa + 8);
        cpasync16(base + OFF_BH + o0, pb);  cpasync16(base + OFF_BH + o1, pb + 8);
        cpasync16(base + OFF_BL + o0, pq);  cpasync16(base + OFF_BL + o1, pq + 8);
    };

    const int rA = wm * 32 + (lane & 15);
    const int swA = rA & 7;
    const int cA = lane >> 4;
    const uint32_t ldA = smbase + rA * 128;
    const int rB = wn * 32 + (lane & 7) + ((lane >> 4) & 1) * 8;
    const int swB = rB & 7;
    const int cBc = (lane >> 3) & 1;
    const uint32_t ldB = smbase + rB * 128;

    auto load_frags = [&](Frags& f, uint32_t so, int kk){
        const uint32_t aoffk = (uint32_t)(((cA + 2 * kk) ^ swA) * 16);
        const uint32_t boffk = (uint32_t)(((cBc + 2 * kk) ^ swB) * 16);
        #pragma unroll
        for (int mf = 0; mf < 2; mf++){
            uint32_t ad = ldA + so + mf * 2048 + aoffk;
            ldsm4(f.ar[mf][0], f.ar[mf][1], f.ar[mf][2], f.ar[mf][3], ad);
        }
        #pragma unroll
        for (int np = 0; np < 2; np++){
            uint32_t bd = ldB + so + OFF_BH + np * 2048 + boffk;
            ldsm4(f.bh[np*2][0], f.bh[np*2][1], f.bh[np*2+1][0], f.bh[np*2+1][1], bd);
            ldsm4(f.bl[np*2][0], f.bl[np*2][1], f.bl[np*2+1][0], f.bl[np*2+1][1], bd + 16384);
        }
    };
    auto do_mmas = [&](Frags& f){
        #pragma unroll
        for (int mf = 0; mf < 2; mf++)
            #pragma unroll
            for (int nf = 0; nf < 4; nf++)
                mma16816(acc[mf][nf], f.ar[mf], f.bh[nf]);
        #pragma unroll
        for (int mf = 0; mf < 2; mf++)
            #pragma unroll
            for (int nf = 0; nf < 4; nf++)
                mma16816(acc[mf][nf], f.ar[mf], f.bl[nf]);
    };

    #pragma unroll
    for (int p = 0; p < STAGES - 1; p++){
        issue(p);
        CP_COMMIT();
    }

    Frags fr[2];
    for (int s = 0; s < S; s++){
        CP_WAIT(STAGES - 2);
        __syncthreads();
        const uint32_t so = (uint32_t)(s & (STAGES - 1)) * STAGE_BYTES;
        load_frags(fr[0], so, 0);
        #pragma unroll
        for (int kk = 0; kk < 4; kk++){
            if (kk < 3) load_frags(fr[(kk + 1) & 1], so, kk + 1);
            do_mmas(fr[kk & 1]);
        }
        int nx = s + STAGES - 1;
        if (nx < S) issue(nx);
        CP_COMMIT();
    }
}

#define ZERO_ACC(acc)                                         \
    float acc[2][4][4];                                       \
    _Pragma("unroll")                                         \
    for (int i = 0; i < 2; i++)                               \
        _Pragma("unroll")                                     \
        for (int j = 0; j < 4; j++)                           \
            _Pragma("unroll")                                 \
            for (int k = 0; k < 4; k++) acc[i][j][k] = 0.f;

// store acc to partial buffer P[col * stride + row]
__device__ __forceinline__ void store_partials(float acc[2][4][4], float* P,
                                               int row0, int col0, size_t stride)
{
    const int lane = threadIdx.x & 31, wid = threadIdx.x >> 5;
    const int wm = wid >> 2, wn = wid & 3;
    const int r0 = row0 + wm * 32 + (lane >> 2);
    const int c0 = col0 + wn * 32 + (lane & 3) * 2;
    #pragma unroll
    for (int mf = 0; mf < 2; mf++){
        #pragma unroll
        for (int nf = 0; nf < 4; nf++){
            int r = r0 + mf * 16, cc = c0 + nf * 8;
            P[(size_t)cc * stride + r]           = acc[mf][nf][0];
            P[(size_t)(cc + 1) * stride + r]     = acc[mf][nf][1];
            P[(size_t)cc * stride + r + 8]       = acc[mf][nf][2];
            P[(size_t)(cc + 1) * stride + r + 8] = acc[mf][nf][3];
        }
    }
}

// ---------------- GEMM 1 (split-K): partials of A @ X ----------------------
__global__ __launch_bounds__(NTHREADS, 1)
void gemm_t_split_kernel(int first)
{
    extern __shared__ char sm[];
    const int row0 = blockIdx.x * BM, col0 = blockIdx.y * BN, z = blockIdx.z;
    const __half* Bh = (first ? g_xTh : g_sTh) + (size_t)col0 * NROWS + (size_t)z * KCHUNK;
    const __half* Bl = (first ? g_xTl : g_sTl) + (size_t)col0 * NROWS + (size_t)z * KCHUNK;

    ZERO_ACC(acc);
    gemm_loop_f16(g_A16 + (size_t)row0 * NROWS + (size_t)z * KCHUNK,
                  Bh, Bl, NROWS, NROWS, KCHUNK / BK, smem_u32(sm), acc);
    store_partials(acc, g_part + (size_t)z * NBP * NMEAS, row0, col0, NMEAS);
}

// ------- reduce gemm_t partials + t epilogue + fused colsum(t^2) -----------
__global__ void reduce_t_kernel(const float* __restrict__ noise, int first)
{
    const int c = blockIdx.y;
    const int row = blockIdx.x * 256 + threadIdx.x;
    float a = 0.f;
    #pragma unroll
    for (int z = 0; z < KSPLIT; z++)
        a += g_part[((size_t)z * NBP + c) * NMEAS + row];
    float v;
    if (first){
        v = noise[(size_t)row * NB + c] + a;
        g_yT[(size_t)c * NMEAS + row] = v;
    } else {
        v = g_yT[(size_t)c * NMEAS + row] - a;
    }
    __half h, l;
    split_h(v, h, l);
    g_tTh[(size_t)c * NMEAS + row] = h;
    g_tTl[(size_t)c * NMEAS + row] = l;

    float sq = v * v;
    #pragma unroll
    for (int o = 16; o; o >>= 1) sq += __shfl_xor_sync(0xffffffffu, sq, o);
    __shared__ float red[8];
    if ((threadIdx.x & 31) == 0) red[threadIdx.x >> 5] = sq;
    __syncthreads();
    if (threadIdx.x < 8){
        float t = red[threadIdx.x];
        #pragma unroll
        for (int o = 4; o; o >>= 1) t += __shfl_xor_sync(0xffu, t, o);
        if (threadIdx.x == 0) atomicAdd(&g_colacc[c], t);
    }
}

// ---------------- GEMM 2 (split-K): partials of W @ t ----------------------
__global__ __launch_bounds__(NTHREADS, 1)
void gemm_s_split_kernel()
{
    extern __shared__ char sm[];
    const int row0 = blockIdx.x * BM, col0 = blockIdx.y * BN, z = blockIdx.z;

    ZERO_ACC(acc);
    gemm_loop_f16(g_W16 + (size_t)row0 * NMEAS + (size_t)z * KCHUNK_S,
                  g_tTh + (size_t)col0 * NMEAS + (size_t)z * KCHUNK_S,
                  g_tTl + (size_t)col0 * NMEAS + (size_t)z * KCHUNK_S,
                  NMEAS, NMEAS, KCHUNK_S / BK, smem_u32(sm), acc);
    store_partials(acc, g_part + (size_t)z * NBP * NROWS, row0, col0, NROWS);
}

// -------- reduce gemm_s partials + s-add + coef + section softmax ----------
// one warp = 32 consecutive rows = exactly one SPARC section, one column
__global__ void reduce_s_kernel(const float* __restrict__ gammap, int iter,
                                float* __restrict__ outp)
{
    const int col = blockIdx.y;
    const int row = blockIdx.x * 256 + threadIdx.x;
    const float g = gammap[iter];

    float a = g_part[(size_t)col * NROWS + row]
            + g_part[((size_t)NBP + col) * NROWS + row];
    float z = a * g;
    if (iter > 0)
        z += __half2float(g_sTh[(size_t)col * NROWS + row])
           + __half2float(g_sTl[(size_t)col * NROWS + row]);
    z *= g_coef[col];

    float m = z;
    #pragma unroll
    for (int o = 16; o; o >>= 1) m = fmaxf(m, __shfl_xor_sync(0xffffffffu, m, o));
    float e = __expf(z - m);
    float su = e;
    #pragma unroll
    for (int o = 16; o; o >>= 1) su += __shfl_xor_sync(0xffffffffu, su, o);
    float v = __fdividef(e, su);

    if (iter == MAXITR - 1){
        outp[(size_t)row * NB + col] = v;
    } else {
        __half h, l;
        split_h(v, h, l);
        g_sTh[(size_t)col * NROWS + row] = h;
        g_sTl[(size_t)col * NROWS + row] = l;
    }
}

// ---------------- prep / small kernels --------------------------------------
__global__ void init_scalars_kernel(){
    if (threadIdx.x == 0) g_taa = 0.0;
    if (threadIdx.x < NBP) g_colacc[threadIdx.x] = 0.f;
}

__global__ void conv_f16_kernel(const float* __restrict__ src,
                                __half* __restrict__ dst, long n4, int do_taa)
{
    double t = 0.0;
    const float4* s4 = (const float4*)src;
    uint2* d2 = (uint2*)dst;
    for (long i = (long)blockIdx.x * blockDim.x + threadIdx.x; i < n4;
         i += (long)gridDim.x * blockDim.x){
        float4 v = s4[i];
        d2[i] = make_uint2(pack_h(__float2half_rn(v.x), __float2half_rn(v.y)),
                           pack_h(__float2half_rn(v.z), __float2half_rn(v.w)));
        if (do_taa)
            t += (double)v.x*v.x + (double)v.y*v.y + (double)v.z*v.z + (double)v.w*v.w;
    }
    if (do_taa){
        __shared__ double smd[256];
        smd[threadIdx.x] = t;
        __syncthreads();
        for (int s = 128; s > 0; s >>= 1){
            if (threadIdx.x < s) smd[threadIdx.x] += smd[threadIdx.x + s];
            __syncthreads();
        }
        if (threadIdx.x == 0) atomicAdd(&g_taa, smd[0]);
    }
}

// fused: blocks [0, 2048) convert W -> g_W16 ; blocks [2048, 2048+8192) transpose x
#define PREP_CONVW_BLOCKS 2048
#define PREP_TRANS_BLOCKS 8192
__global__ void prep2_kernel(const float* __restrict__ W, const float* __restrict__ x)
{
    if (blockIdx.x < PREP_CONVW_BLOCKS){
        const long n4 = (long)NROWS * NMEAS / 4;
        const float4* s4 = (const float4*)W;
        uint2* d2 = (uint2*)g_W16;
        for (long i = (long)blockIdx.x * 256 + threadIdx.x; i < n4;
             i += (long)PREP_CONVW_BLOCKS * 256){
            float4 v = s4[i];
            d2[i] = make_uint2(pack_h(__float2half_rn(v.x), __float2half_rn(v.y)),
                               pack_h(__float2half_rn(v.z), __float2half_rn(v.w)));
        }
    } else {
        __shared__ float tile[32][33];
        int b = blockIdx.x - PREP_CONVW_BLOCKS;        // 8192 blocks: (512, 16)
        int k0 = (b & 511) * 32, n0 = (b >> 9) * 32;
        int tx = threadIdx.x & 31, ty = threadIdx.x >> 5;   // (32, 8)
        #pragma unroll
        for (int i = 0; i < 32; i += 8){
            int k = k0 + ty + i, n = n0 + tx;
            tile[ty + i][tx] = (n < NB) ? x[(size_t)k * NB + n] : 0.f;
        }
        __syncthreads();
        #pragma unroll
        for (int i = 0; i < 32; i += 8){
            int n = n0 + ty + i, k = k0 + tx;
            float v = tile[tx][ty + i];
            __half h, l;
            split_h(v, h, l);
            g_xTh[(size_t)n * NROWS + k] = h;
            g_xTl[(size_t)n * NROWS + k] = l;
        }
    }
}

__global__ void finalize_kernel(const float* __restrict__ gamma, int iter){
    int c = threadIdx.x;
    if (c < NB){
        float taa = (float)g_taa;
        float tww = taa;
        float g = gamma[iter];
        float v2 = (g_colacc[c] - (float)MSEC * SIGMA2f) / taa;
        float tau2 = v2 / (float)NROWS * ((float)NROWS + (g*g - 2.0f*g) * (float)MSEC)
                   + g * g * tww * SIGMA2f / (float)NROWS;
        g_coef[c] = SCALEf / tau2;
    }
    if (c < NBP) g_colacc[c] = 0.f;
}

// ---------------- launch ----------------------------------------------------
extern "C" void kernel_launch(void* const* d_in, const int* in_sizes, int n_in,
                              void* d_out, int out_size)
{
    const float* x     = (const float*)d_in[0];
    const float* noise = (const float*)d_in[2];
    const float* A     = (const float*)d_in[3];
    const float* W     = (const float*)d_in[4];
    const float* gamma = (const float*)d_in[5];
    float* out = (float*)d_out;

    cudaFuncSetAttribute((const void*)gemm_t_split_kernel,
                         cudaFuncAttributeMaxDynamicSharedMemorySize, DYN_SMEM);
    cudaFuncSetAttribute((const void*)gemm_s_split_kernel,
                         cudaFuncAttributeMaxDynamicSharedMemorySize, DYN_SMEM);

    __half *dA16;
    cudaGetSymbolAddress((void**)&dA16, g_A16);

    const long n4 = (long)NMEAS * NROWS / 4;

    // launch order arranged so the 4th launch (ncu capture target) = gemm_t_split
    init_scalars_kernel<<<1, 512>>>();                               // 1
    conv_f16_kernel<<<2048, 256>>>(A, dA16, n4, 1);                  // 2 (A + taa)
    prep2_kernel<<<PREP_CONVW_BLOCKS + PREP_TRANS_BLOCKS, 256>>>(W, x); // 3 (W + xT)

    // y = A x + noise (t0 = y)
    gemm_t_split_kernel<<<dim3(NMEAS/BM, NBP/BN, KSPLIT), NTHREADS, DYN_SMEM>>>(1); // 4
    reduce_t_kernel<<<dim3(NMEAS/256, NB), 256>>>(noise, 1);

    for (int it = 0; it < MAXITR; it++){
        finalize_kernel<<<1, 512>>>(gamma, it);
        gemm_s_split_kernel<<<dim3(NROWS/BM, NBP/BN, KSPLIT_S), NTHREADS, DYN_SMEM>>>();
        reduce_s_kernel<<<dim3(NROWS/256, NB), 256>>>(gamma, it, out);
        if (it < MAXITR - 1){
            gemm_t_split_kernel<<<dim3(NMEAS/BM, NBP/BN, KSPLIT), NTHREADS, DYN_SMEM>>>(0);
            reduce_t_kernel<<<dim3(NMEAS/256, NB), 256>>>(noise, 0);
        }
    }
}